// round 1
// baseline (speedup 1.0000x reference)
#include <cuda_runtime.h>

#define NB 2
#define ND 8
#define NNODE 40
#define NH 128
#define HID 512
#define NJK (NNODE * NNODE)   // 1600
#define KC 16                 // k-chunk for main GEMM
#define ROWS 64               // jk rows per CTA

// Scratch (allocation-free rule: __device__ globals)
__device__ float g_A[NB * NNODE * HID];   // hn              [b][i][n]
__device__ float g_C[NB * NJK * HID];     // hp + b1         [b][jk][n]

typedef unsigned long long ull;

__device__ __forceinline__ ull pack2(float lo, float hi) {
    ull r;
    asm("mov.b64 %0, {%1, %2};" : "=l"(r) : "f"(lo), "f"(hi));
    return r;
}
__device__ __forceinline__ void unpack2(ull v, float& lo, float& hi) {
    asm("mov.b64 {%0, %1}, %2;" : "=f"(lo), "=f"(hi) : "l"(v));
}
__device__ __forceinline__ ull fma2(ull a, ull b, ull c) {
    ull d;
    asm("fma.rn.f32x2 %0, %1, %2, %3;" : "=l"(d) : "l"(a), "l"(b), "l"(c));
    return d;
}

// ---------------------------------------------------------------------------
// Kernel A: nf = max_d(node_feature); g_A[b][i][:] = nf @ W1n
// grid = B*N CTAs, 128 threads
// ---------------------------------------------------------------------------
__global__ void k_node(const float* __restrict__ nfin,
                       const float* __restrict__ W1n) {
    __shared__ float s[NH];
    int bi = blockIdx.x;              // b*NNODE + i
    int t  = threadIdx.x;             // 0..127
    int b  = bi / NNODE, i = bi % NNODE;

    const float* base = nfin + (((size_t)b * ND) * NNODE + i) * NH + t;
    float m = base[0];
#pragma unroll
    for (int d = 1; d < ND; d++)
        m = fmaxf(m, base[(size_t)d * NNODE * NH]);
    s[t] = m;
    __syncthreads();

    float a0 = 0.f, a1 = 0.f, a2 = 0.f, a3 = 0.f;
    const float* w = W1n + t * 4;
#pragma unroll 8
    for (int h = 0; h < NH; h++) {
        float4 wv = *(const float4*)(w + (size_t)h * HID);
        float x = s[h];
        a0 = fmaf(x, wv.x, a0);
        a1 = fmaf(x, wv.y, a1);
        a2 = fmaf(x, wv.z, a2);
        a3 = fmaf(x, wv.w, a3);
    }
    float4 o = {a0, a1, a2, a3};
    *(float4*)(g_A + (size_t)bi * HID + t * 4) = o;
}

// ---------------------------------------------------------------------------
// Kernel B: pf = max_d(pairwise_feature); g_C[b][jk][:] = pf @ W1p + b1
// grid = B*N*N CTAs, 128 threads
// ---------------------------------------------------------------------------
__global__ void k_pair(const float* __restrict__ pfin,
                       const float* __restrict__ W1p,
                       const float* __restrict__ b1) {
    __shared__ float s[NH];
    int r = blockIdx.x;               // b*NJK + jk
    int t = threadIdx.x;
    int b = r / NJK, jk = r % NJK;

    const float* base = pfin + (((size_t)b * ND) * NJK + jk) * NH + t;
    float m = base[0];
#pragma unroll
    for (int d = 1; d < ND; d++)
        m = fmaxf(m, base[(size_t)d * NJK * NH]);
    s[t] = m;
    __syncthreads();

    float4 bv = *(const float4*)(b1 + t * 4);
    float a0 = bv.x, a1 = bv.y, a2 = bv.z, a3 = bv.w;
    const float* w = W1p + t * 4;
#pragma unroll 8
    for (int h = 0; h < NH; h++) {
        float4 wv = *(const float4*)(w + (size_t)h * HID);
        float x = s[h];
        a0 = fmaf(x, wv.x, a0);
        a1 = fmaf(x, wv.y, a1);
        a2 = fmaf(x, wv.z, a2);
        a3 = fmaf(x, wv.w, a3);
    }
    float4 o = {a0, a1, a2, a3};
    *(float4*)(g_C + (size_t)r * HID + t * 4) = o;
}

// ---------------------------------------------------------------------------
// Kernel C (dominant): for each (b, i, jk-tile of 64):
//   h1 = relu(A[b,i,:] + C[b,jk,:])            (recomputed per k-chunk, smem)
//   out = sigmoid(scale*(relu(h1@W2 + b2)@W3 + b3) + bias)
// 256 threads = 8 warps; warp ty owns rows 8ty..8ty+7 (4 f32x2 row-pairs),
// lane tx owns n = tx + 32*nn (nn=0..15) -> full 512 n per warp.
// acc[4][16] f32x2 accumulators persist across k; epilogue fuses
// relu + W3-dot + warp shfl reduction + sigmoid.
// ---------------------------------------------------------------------------
__global__ __launch_bounds__(256, 1)
void k_main(const float* __restrict__ W2,
            const float* __restrict__ b2,
            const float* __restrict__ W3,
            const float* __restrict__ b3,
            const float* __restrict__ pscale,
            const float* __restrict__ pbias,
            float* __restrict__ out) {
    __shared__ float W2s[KC][HID];        // 32 KB
    __shared__ float H1s[KC][ROWS + 1];   // pad -> conflict-lean stores
    __shared__ float As[HID];

    int b  = blockIdx.z;
    int i  = blockIdx.y;
    int jt = blockIdx.x;                  // jk tile: rows jt*64 .. jt*64+63
    int tid = threadIdx.x;
    int tx = tid & 31, ty = tid >> 5;

    const float* Arow = g_A + ((size_t)b * NNODE + i) * HID;
    for (int t = tid; t < HID; t += 256) As[t] = Arow[t];

    const float* Cbase = g_C + ((size_t)b * NJK + jt * ROWS) * HID;

    ull acc[4][16];
#pragma unroll
    for (int p = 0; p < 4; p++)
#pragma unroll
        for (int q = 0; q < 16; q++) acc[p][q] = 0ull;

    int cr = tid >> 2;            // 0..63 : jk row handled by this thread
    int ck = (tid & 3) * 4;       // 0,4,8,12 : k offset within chunk
    const float* cptr = Cbase + (size_t)cr * HID + ck;

    for (int kc = 0; kc < HID; kc += KC) {
        __syncthreads();   // previous chunk fully consumed before overwrite
        // stage W2 chunk: KC*HID = 8192 floats, 8 float4 per thread
        {
            const float4* wsrc = (const float4*)(W2 + (size_t)kc * HID);
            float4* wdst = (float4*)&W2s[0][0];
#pragma unroll
            for (int q = 0; q < 8; q++)
                wdst[tid + q * 256] = wsrc[tid + q * 256];
        }
        // stage h1 chunk: relu(A + C)
        {
            float4 cv = *(const float4*)(cptr + kc);
            H1s[ck + 0][cr] = fmaxf(As[kc + ck + 0] + cv.x, 0.f);
            H1s[ck + 1][cr] = fmaxf(As[kc + ck + 1] + cv.y, 0.f);
            H1s[ck + 2][cr] = fmaxf(As[kc + ck + 2] + cv.z, 0.f);
            H1s[ck + 3][cr] = fmaxf(As[kc + ck + 3] + cv.w, 0.f);
        }
        __syncthreads();

#pragma unroll
        for (int kk = 0; kk < KC; kk++) {
            // broadcast loads: 8 rows of h1 for this warp
            float r0 = H1s[kk][8 * ty + 0];
            float r1 = H1s[kk][8 * ty + 1];
            float r2 = H1s[kk][8 * ty + 2];
            float r3 = H1s[kk][8 * ty + 3];
            float r4 = H1s[kk][8 * ty + 4];
            float r5 = H1s[kk][8 * ty + 5];
            float r6 = H1s[kk][8 * ty + 6];
            float r7 = H1s[kk][8 * ty + 7];
            ull ap0 = pack2(r0, r1);
            ull ap1 = pack2(r2, r3);
            ull ap2 = pack2(r4, r5);
            ull ap3 = pack2(r6, r7);
            const float* wr = &W2s[kk][tx];
#pragma unroll
            for (int nn = 0; nn < 16; nn++) {
                float w = wr[nn * 32];
                ull wp = pack2(w, w);
                acc[0][nn] = fma2(ap0, wp, acc[0][nn]);
                acc[1][nn] = fma2(ap1, wp, acc[1][nn]);
                acc[2][nn] = fma2(ap2, wp, acc[2][nn]);
                acc[3][nn] = fma2(ap3, wp, acc[3][nn]);
            }
        }
    }

    // Epilogue: relu(acc + b2) * W3, reduce over n (lanes), sigmoid
    float part[8];
#pragma unroll
    for (int r = 0; r < 8; r++) part[r] = 0.f;
#pragma unroll
    for (int nn = 0; nn < 16; nn++) {
        int n = tx + nn * 32;
        float bb = __ldg(&b2[n]);
        float w3 = __ldg(&W3[n]);
#pragma unroll
        for (int p = 0; p < 4; p++) {
            float lo, hi;
            unpack2(acc[p][nn], lo, hi);
            part[2 * p + 0] += fmaxf(lo + bb, 0.f) * w3;
            part[2 * p + 1] += fmaxf(hi + bb, 0.f) * w3;
        }
    }
#pragma unroll
    for (int r = 0; r < 8; r++) {
#pragma unroll
        for (int s = 16; s > 0; s >>= 1)
            part[r] += __shfl_xor_sync(0xffffffffu, part[r], s);
    }
    if (tx == 0) {
        float b3v = b3[0];
        float sc  = pscale[0];
        float bi2 = pbias[0];
        size_t obase = ((size_t)b * NNODE + i) * NJK + (size_t)jt * ROWS + 8 * ty;
#pragma unroll
        for (int r = 0; r < 8; r++) {
            float v = sc * (part[r] + b3v) + bi2;
            out[obase + r] = 1.f / (1.f + expf(-v));
        }
    }
}

// ---------------------------------------------------------------------------
extern "C" void kernel_launch(void* const* d_in, const int* in_sizes, int n_in,
                              void* d_out, int out_size) {
    const float* node = (const float*)d_in[0];
    const float* pair = (const float*)d_in[1];
    const float* W1n  = (const float*)d_in[2];
    const float* W1p  = (const float*)d_in[3];
    const float* b1   = (const float*)d_in[4];
    const float* W2   = (const float*)d_in[5];
    const float* b2   = (const float*)d_in[6];
    const float* W3   = (const float*)d_in[7];
    const float* b3   = (const float*)d_in[8];
    const float* sc   = (const float*)d_in[9];
    const float* bi   = (const float*)d_in[10];
    float* out = (float*)d_out;

    k_node<<<NB * NNODE, NH>>>(node, W1n);
    k_pair<<<NB * NJK, NH>>>(pair, W1p, b1);

    dim3 grid(NJK / ROWS, NNODE, NB);   // 25 x 40 x 2 = 2000 CTAs
    k_main<<<grid, 256>>>(W2, b2, W3, b3, sc, bi, out);
}

// round 2
// speedup vs baseline: 1.0010x; 1.0010x over previous
#include <cuda_runtime.h>

#define NB 2
#define ND 8
#define NNODE 40
#define NH 128
#define HID 512
#define NJK (NNODE * NNODE)   // 1600
#define KC 16                 // k-chunk for main GEMM
#define ROWS 64               // jk rows per CTA

// Scratch (allocation-free rule: __device__ globals)
__device__ float g_A[NB * NNODE * HID];   // hn              [b][i][n]
__device__ float g_C[NB * NJK * HID];     // hp + b1         [b][jk][n]

typedef unsigned long long ull;

__device__ __forceinline__ ull pack2(float lo, float hi) {
    ull r;
    asm("mov.b64 %0, {%1, %2};" : "=l"(r) : "f"(lo), "f"(hi));
    return r;
}
__device__ __forceinline__ void unpack2(ull v, float& lo, float& hi) {
    asm("mov.b64 {%0, %1}, %2;" : "=f"(lo), "=f"(hi) : "l"(v));
}
__device__ __forceinline__ ull fma2(ull a, ull b, ull c) {
    ull d;
    asm("fma.rn.f32x2 %0, %1, %2, %3;" : "=l"(d) : "l"(a), "l"(b), "l"(c));
    return d;
}

// ---------------------------------------------------------------------------
// Kernel A: nf = max_d(node_feature); g_A[b][i][:] = nf @ W1n
// grid = B*N CTAs, 128 threads
// ---------------------------------------------------------------------------
__global__ void k_node(const float* __restrict__ nfin,
                       const float* __restrict__ W1n) {
    __shared__ float s[NH];
    int bi = blockIdx.x;              // b*NNODE + i
    int t  = threadIdx.x;             // 0..127
    int b  = bi / NNODE, i = bi % NNODE;

    const float* base = nfin + (((size_t)b * ND) * NNODE + i) * NH + t;
    float m = base[0];
#pragma unroll
    for (int d = 1; d < ND; d++)
        m = fmaxf(m, base[(size_t)d * NNODE * NH]);
    s[t] = m;
    __syncthreads();

    float a0 = 0.f, a1 = 0.f, a2 = 0.f, a3 = 0.f;
    const float* w = W1n + t * 4;
#pragma unroll 8
    for (int h = 0; h < NH; h++) {
        float4 wv = *(const float4*)(w + (size_t)h * HID);
        float x = s[h];
        a0 = fmaf(x, wv.x, a0);
        a1 = fmaf(x, wv.y, a1);
        a2 = fmaf(x, wv.z, a2);
        a3 = fmaf(x, wv.w, a3);
    }
    float4 o = {a0, a1, a2, a3};
    *(float4*)(g_A + (size_t)bi * HID + t * 4) = o;
}

// ---------------------------------------------------------------------------
// Kernel B: pf = max_d(pairwise_feature); g_C[b][jk][:] = pf @ W1p + b1
// grid = B*N*N CTAs, 128 threads
// ---------------------------------------------------------------------------
__global__ void k_pair(const float* __restrict__ pfin,
                       const float* __restrict__ W1p,
                       const float* __restrict__ b1) {
    __shared__ float s[NH];
    int r = blockIdx.x;               // b*NJK + jk
    int t = threadIdx.x;
    int b = r / NJK, jk = r % NJK;

    const float* base = pfin + (((size_t)b * ND) * NJK + jk) * NH + t;
    float m = base[0];
#pragma unroll
    for (int d = 1; d < ND; d++)
        m = fmaxf(m, base[(size_t)d * NJK * NH]);
    s[t] = m;
    __syncthreads();

    float4 bv = *(const float4*)(b1 + t * 4);
    float a0 = bv.x, a1 = bv.y, a2 = bv.z, a3 = bv.w;
    const float* w = W1p + t * 4;
#pragma unroll 8
    for (int h = 0; h < NH; h++) {
        float4 wv = *(const float4*)(w + (size_t)h * HID);
        float x = s[h];
        a0 = fmaf(x, wv.x, a0);
        a1 = fmaf(x, wv.y, a1);
        a2 = fmaf(x, wv.z, a2);
        a3 = fmaf(x, wv.w, a3);
    }
    float4 o = {a0, a1, a2, a3};
    *(float4*)(g_C + (size_t)r * HID + t * 4) = o;
}

// ---------------------------------------------------------------------------
// Kernel C (dominant): for each (b, i, jk-tile of 64):
//   h1 = relu(A[b,i,:] + C[b,jk,:])            (recomputed per k-chunk, smem)
//   out = sigmoid(scale*(relu(h1@W2 + b2)@W3 + b3) + bias)
// 256 threads = 8 warps; warp ty owns rows 8ty..8ty+7 (4 f32x2 row-pairs),
// lane tx owns n = tx + 32*nn (nn=0..15) -> full 512 n per warp.
// acc[4][16] f32x2 accumulators persist across k; epilogue fuses
// relu + W3-dot + warp shfl reduction + sigmoid.
// ---------------------------------------------------------------------------
__global__ __launch_bounds__(256, 1)
void k_main(const float* __restrict__ W2,
            const float* __restrict__ b2,
            const float* __restrict__ W3,
            const float* __restrict__ b3,
            const float* __restrict__ pscale,
            const float* __restrict__ pbias,
            float* __restrict__ out) {
    __shared__ float W2s[KC][HID];        // 32 KB
    __shared__ float H1s[KC][ROWS + 1];   // pad -> conflict-lean stores
    __shared__ float As[HID];

    int b  = blockIdx.z;
    int i  = blockIdx.y;
    int jt = blockIdx.x;                  // jk tile: rows jt*64 .. jt*64+63
    int tid = threadIdx.x;
    int tx = tid & 31, ty = tid >> 5;

    const float* Arow = g_A + ((size_t)b * NNODE + i) * HID;
    for (int t = tid; t < HID; t += 256) As[t] = Arow[t];

    const float* Cbase = g_C + ((size_t)b * NJK + jt * ROWS) * HID;

    ull acc[4][16];
#pragma unroll
    for (int p = 0; p < 4; p++)
#pragma unroll
        for (int q = 0; q < 16; q++) acc[p][q] = 0ull;

    int cr = tid >> 2;            // 0..63 : jk row handled by this thread
    int ck = (tid & 3) * 4;       // 0,4,8,12 : k offset within chunk
    const float* cptr = Cbase + (size_t)cr * HID + ck;

    for (int kc = 0; kc < HID; kc += KC) {
        __syncthreads();   // previous chunk fully consumed before overwrite
        // stage W2 chunk: KC*HID = 8192 floats, 8 float4 per thread
        {
            const float4* wsrc = (const float4*)(W2 + (size_t)kc * HID);
            float4* wdst = (float4*)&W2s[0][0];
#pragma unroll
            for (int q = 0; q < 8; q++)
                wdst[tid + q * 256] = wsrc[tid + q * 256];
        }
        // stage h1 chunk: relu(A + C)
        {
            float4 cv = *(const float4*)(cptr + kc);
            H1s[ck + 0][cr] = fmaxf(As[kc + ck + 0] + cv.x, 0.f);
            H1s[ck + 1][cr] = fmaxf(As[kc + ck + 1] + cv.y, 0.f);
            H1s[ck + 2][cr] = fmaxf(As[kc + ck + 2] + cv.z, 0.f);
            H1s[ck + 3][cr] = fmaxf(As[kc + ck + 3] + cv.w, 0.f);
        }
        __syncthreads();

#pragma unroll
        for (int kk = 0; kk < KC; kk++) {
            // broadcast loads: 8 rows of h1 for this warp
            float r0 = H1s[kk][8 * ty + 0];
            float r1 = H1s[kk][8 * ty + 1];
            float r2 = H1s[kk][8 * ty + 2];
            float r3 = H1s[kk][8 * ty + 3];
            float r4 = H1s[kk][8 * ty + 4];
            float r5 = H1s[kk][8 * ty + 5];
            float r6 = H1s[kk][8 * ty + 6];
            float r7 = H1s[kk][8 * ty + 7];
            ull ap0 = pack2(r0, r1);
            ull ap1 = pack2(r2, r3);
            ull ap2 = pack2(r4, r5);
            ull ap3 = pack2(r6, r7);
            const float* wr = &W2s[kk][tx];
#pragma unroll
            for (int nn = 0; nn < 16; nn++) {
                float w = wr[nn * 32];
                ull wp = pack2(w, w);
                acc[0][nn] = fma2(ap0, wp, acc[0][nn]);
                acc[1][nn] = fma2(ap1, wp, acc[1][nn]);
                acc[2][nn] = fma2(ap2, wp, acc[2][nn]);
                acc[3][nn] = fma2(ap3, wp, acc[3][nn]);
            }
        }
    }

    // Epilogue: relu(acc + b2) * W3, reduce over n (lanes), sigmoid
    float part[8];
#pragma unroll
    for (int r = 0; r < 8; r++) part[r] = 0.f;
#pragma unroll
    for (int nn = 0; nn < 16; nn++) {
        int n = tx + nn * 32;
        float bb = __ldg(&b2[n]);
        float w3 = __ldg(&W3[n]);
#pragma unroll
        for (int p = 0; p < 4; p++) {
            float lo, hi;
            unpack2(acc[p][nn], lo, hi);
            part[2 * p + 0] += fmaxf(lo + bb, 0.f) * w3;
            part[2 * p + 1] += fmaxf(hi + bb, 0.f) * w3;
        }
    }
#pragma unroll
    for (int r = 0; r < 8; r++) {
#pragma unroll
        for (int s = 16; s > 0; s >>= 1)
            part[r] += __shfl_xor_sync(0xffffffffu, part[r], s);
    }
    if (tx == 0) {
        float b3v = b3[0];
        float sc  = pscale[0];
        float bi2 = pbias[0];
        size_t obase = ((size_t)b * NNODE + i) * NJK + (size_t)jt * ROWS + 8 * ty;
#pragma unroll
        for (int r = 0; r < 8; r++) {
            float v = sc * (part[r] + b3v) + bi2;
            out[obase + r] = 1.f / (1.f + expf(-v));
        }
    }
}

// ---------------------------------------------------------------------------
extern "C" void kernel_launch(void* const* d_in, const int* in_sizes, int n_in,
                              void* d_out, int out_size) {
    const float* node = (const float*)d_in[0];
    const float* pair = (const float*)d_in[1];
    const float* W1n  = (const float*)d_in[2];
    const float* W1p  = (const float*)d_in[3];
    const float* b1   = (const float*)d_in[4];
    const float* W2   = (const float*)d_in[5];
    const float* b2   = (const float*)d_in[6];
    const float* W3   = (const float*)d_in[7];
    const float* b3   = (const float*)d_in[8];
    const float* sc   = (const float*)d_in[9];
    const float* bi   = (const float*)d_in[10];
    float* out = (float*)d_out;

    k_node<<<NB * NNODE, NH>>>(node, W1n);
    k_pair<<<NB * NJK, NH>>>(pair, W1p, b1);

    dim3 grid(NJK / ROWS, NNODE, NB);   // 25 x 40 x 2 = 2000 CTAs
    k_main<<<grid, 256>>>(W2, b2, W3, b3, sc, bi, out);
}

// round 5
// speedup vs baseline: 2.7609x; 2.7581x over previous
#include <cuda_runtime.h>
#include <cstdint>

#define NB 2
#define ND 8
#define NNODE 40
#define NH 128
#define HID 512
#define NJK (NNODE * NNODE)        // 1600
#define ROWS_PER_B (NNODE * NJK)   // 64000
#define TILE_M 128
#define TILE_N 128                 // N-slice per pass
#define NPASS (HID / TILE_N)       // 4
#define KCH 32                     // k per chunk
#define NCHUNKS (HID / KCH)        // 16

// A smem row stride 36 floats -> frag bank (4g+tig)%32 conflict-free
#define AST 36
// B smem row stride 136 floats -> frag bank (8t+g)%32 conflict-free
#define BST 136

// -------- device scratch (allocation-free rule) --------
__device__ float g_A[NB * NNODE * HID];   // hn        [b][i][k]
__device__ float g_C[NB * NJK * HID];     // hp + b1   [b][jk][k]

// -------- dynamic smem layout (bytes) --------
#define SM_AOFF   0                        // 128 ints
#define SM_COFF   512                      // 128 ints
#define SM_BW     1024                     // 512 float2 (b2, W3)
#define SM_VRED   5120                     // 256 floats
#define SM_A0     6144                     // 128*36*4 = 18432
#define SM_A1     24576
#define SM_B0     43008                    // 32*136*4 = 17408
#define SM_B1     60416
#define SM_TOTAL  77824

__device__ __forceinline__ float tf32r(float x) {
    float y;
    asm("cvt.rna.tf32.f32 %0, %1;" : "=f"(y) : "f"(x));
    return y;
}
__device__ __forceinline__ void mma_tf32(float* d, const uint32_t* a,
                                         uint32_t b0, uint32_t b1) {
    asm volatile(
        "mma.sync.aligned.m16n8k8.row.col.f32.tf32.tf32.f32 "
        "{%0,%1,%2,%3}, {%4,%5,%6,%7}, {%8,%9}, {%0,%1,%2,%3};"
        : "+f"(d[0]), "+f"(d[1]), "+f"(d[2]), "+f"(d[3])
        : "r"(a[0]), "r"(a[1]), "r"(a[2]), "r"(a[3]), "r"(b0), "r"(b1));
}

// ---------------------------------------------------------------------------
// Kernel A: nf = max_d(node_feature); g_A[b][i][:] = nf @ W1n
// ---------------------------------------------------------------------------
__global__ void k_node(const float* __restrict__ nfin,
                       const float* __restrict__ W1n) {
    __shared__ float s[NH];
    int bi = blockIdx.x;
    int t  = threadIdx.x;
    int b  = bi / NNODE, i = bi % NNODE;

    const float* base = nfin + (((size_t)b * ND) * NNODE + i) * NH + t;
    float m = base[0];
#pragma unroll
    for (int d = 1; d < ND; d++)
        m = fmaxf(m, base[(size_t)d * NNODE * NH]);
    s[t] = m;
    __syncthreads();

    float a0 = 0.f, a1 = 0.f, a2 = 0.f, a3 = 0.f;
    const float* w = W1n + t * 4;
#pragma unroll 8
    for (int h = 0; h < NH; h++) {
        float4 wv = *(const float4*)(w + (size_t)h * HID);
        float x = s[h];
        a0 = fmaf(x, wv.x, a0);
        a1 = fmaf(x, wv.y, a1);
        a2 = fmaf(x, wv.z, a2);
        a3 = fmaf(x, wv.w, a3);
    }
    float4 o = {a0, a1, a2, a3};
    *(float4*)(g_A + (size_t)bi * HID + t * 4) = o;
}

// ---------------------------------------------------------------------------
// Kernel B: pf = max_d(pairwise_feature); g_C[b][jk][:] = pf @ W1p + b1
// ---------------------------------------------------------------------------
__global__ void k_pair(const float* __restrict__ pfin,
                       const float* __restrict__ W1p,
                       const float* __restrict__ b1) {
    __shared__ float s[NH];
    int r = blockIdx.x;
    int t = threadIdx.x;
    int b = r / NJK, jk = r % NJK;

    const float* base = pfin + (((size_t)b * ND) * NJK + jk) * NH + t;
    float m = base[0];
#pragma unroll
    for (int d = 1; d < ND; d++)
        m = fmaxf(m, base[(size_t)d * NJK * NH]);
    s[t] = m;
    __syncthreads();

    float4 bv = *(const float4*)(b1 + t * 4);
    float a0 = bv.x, a1 = bv.y, a2 = bv.z, a3 = bv.w;
    const float* w = W1p + t * 4;
#pragma unroll 8
    for (int h = 0; h < NH; h++) {
        float4 wv = *(const float4*)(w + (size_t)h * HID);
        float x = s[h];
        a0 = fmaf(x, wv.x, a0);
        a1 = fmaf(x, wv.y, a1);
        a2 = fmaf(x, wv.z, a2);
        a3 = fmaf(x, wv.w, a3);
    }
    float4 o = {a0, a1, a2, a3};
    *(float4*)(g_C + (size_t)r * HID + t * 4) = o;
}

// ---------------------------------------------------------------------------
// Kernel C: mma.sync tf32 GEMM, fully fused MLP tail.
//   8 warps: wm = wid&3 (M 32-blocks), wn = wid>>2 (N 64-blocks of the 128 slice)
//   warp tile 32 x 64, acc[2][8][4]; 4 N-passes; K double-buffered in 32-chunks.
// ---------------------------------------------------------------------------
__global__ __launch_bounds__(256, 1)
void k_main(const float* __restrict__ W2, const float* __restrict__ b2,
            const float* __restrict__ W3, const float* __restrict__ b3,
            const float* __restrict__ psc, const float* __restrict__ pbi,
            float* __restrict__ out) {
    extern __shared__ char smem[];
    int* aoff = (int*)(smem + SM_AOFF);
    int* coff = (int*)(smem + SM_COFF);
    float2* bw = (float2*)(smem + SM_BW);
    float* vred = (float*)(smem + SM_VRED);

    int tid = threadIdx.x;
    int wid = tid >> 5, lane = tid & 31;
    int g = lane >> 2, tig = lane & 3;
    int wm = wid & 3, wn = wid >> 2;
    int b  = blockIdx.y;
    int t0 = blockIdx.x * TILE_M;

    if (tid < TILE_M) {
        int rr = t0 + tid;
        int i  = rr / NJK;
        int jk = rr - i * NJK;
        aoff[tid] = (b * NNODE + i) * HID;
        coff[tid] = (b * NJK + jk) * HID;
    }
    for (int n = tid; n < HID; n += 256)
        bw[n] = make_float2(b2[n], W3[n]);
    __syncthreads();

    // per-thread staging indices
    const int sm_m = tid >> 3, sm_e = tid & 7;       // A: 4 iters cover 128x32
    const int sm_k = tid >> 5, sm_e2 = tid & 31;     // B: 4 iters cover 32x128

    float v[4] = {0.f, 0.f, 0.f, 0.f};

    for (int np = 0; np < NPASS; np++) {
        int n0 = np * TILE_N;
        float acc[2][8][4];
#pragma unroll
        for (int mt = 0; mt < 2; mt++)
#pragma unroll
            for (int nt = 0; nt < 8; nt++)
#pragma unroll
                for (int j = 0; j < 4; j++) acc[mt][nt][j] = 0.f;

        // ---- stage chunk 0 into buffer 0 ----
        {
            float* As = (float*)(smem + SM_A0);
            float* Bs = (float*)(smem + SM_B0);
#pragma unroll
            for (int q = 0; q < 4; q++) {
                int m = sm_m + q * 32, e4 = 4 * sm_e;
                float4 av = *(const float4*)(g_A + aoff[m] + e4);
                float4 cv = *(const float4*)(g_C + coff[m] + e4);
                float4 h;
                h.x = tf32r(fmaxf(av.x + cv.x, 0.f));
                h.y = tf32r(fmaxf(av.y + cv.y, 0.f));
                h.z = tf32r(fmaxf(av.z + cv.z, 0.f));
                h.w = tf32r(fmaxf(av.w + cv.w, 0.f));
                *(float4*)(As + m * AST + e4) = h;
                int k = sm_k + q * 8, f4 = 4 * sm_e2;
                float4 wv = *(const float4*)(W2 + (size_t)k * HID + n0 + f4);
                wv.x = tf32r(wv.x); wv.y = tf32r(wv.y);
                wv.z = tf32r(wv.z); wv.w = tf32r(wv.w);
                *(float4*)(Bs + k * BST + f4) = wv;
            }
        }
        __syncthreads();

        int buf = 0;
        for (int c = 0; c < NCHUNKS; c++) {
            float4 pa[4], pc[4], pb[4];
            if (c + 1 < NCHUNKS) {
                int kc = (c + 1) * KCH;
#pragma unroll
                for (int q = 0; q < 4; q++) {
                    int m = sm_m + q * 32, e4 = 4 * sm_e;
                    pa[q] = *(const float4*)(g_A + aoff[m] + kc + e4);
                    pc[q] = *(const float4*)(g_C + coff[m] + kc + e4);
                    int k = sm_k + q * 8, f4 = 4 * sm_e2;
                    pb[q] = *(const float4*)(W2 + (size_t)(kc + k) * HID + n0 + f4);
                }
            }

            // ---- compute current buffer ----
            const float* As = (const float*)(smem + (buf ? SM_A1 : SM_A0));
            const float* Bs = (const float*)(smem + (buf ? SM_B1 : SM_B0));
#pragma unroll
            for (int ks = 0; ks < 4; ks++) {
                uint32_t afr[2][4];
#pragma unroll
                for (int mt = 0; mt < 2; mt++) {
                    int r0 = wm * 32 + mt * 16 + g;
                    afr[mt][0] = __float_as_uint(As[r0 * AST + ks * 8 + tig]);
                    afr[mt][1] = __float_as_uint(As[(r0 + 8) * AST + ks * 8 + tig]);
                    afr[mt][2] = __float_as_uint(As[r0 * AST + ks * 8 + tig + 4]);
                    afr[mt][3] = __float_as_uint(As[(r0 + 8) * AST + ks * 8 + tig + 4]);
                }
#pragma unroll
                for (int nt = 0; nt < 8; nt++) {
                    int bc = wn * 64 + nt * 8 + g;
                    uint32_t b0 = __float_as_uint(Bs[(ks * 8 + tig) * BST + bc]);
                    uint32_t b1 = __float_as_uint(Bs[(ks * 8 + tig + 4) * BST + bc]);
                    mma_tf32(acc[0][nt], afr[0], b0, b1);
                    mma_tf32(acc[1][nt], afr[1], b0, b1);
                }
            }

            // ---- commit prefetched chunk to other buffer ----
            if (c + 1 < NCHUNKS) {
                float* Asn = (float*)(smem + (buf ? SM_A0 : SM_A1));
                float* Bsn = (float*)(smem + (buf ? SM_B0 : SM_B1));
#pragma unroll
                for (int q = 0; q < 4; q++) {
                    int m = sm_m + q * 32, e4 = 4 * sm_e;
                    float4 h;
                    h.x = tf32r(fmaxf(pa[q].x + pc[q].x, 0.f));
                    h.y = tf32r(fmaxf(pa[q].y + pc[q].y, 0.f));
                    h.z = tf32r(fmaxf(pa[q].z + pc[q].z, 0.f));
                    h.w = tf32r(fmaxf(pa[q].w + pc[q].w, 0.f));
                    *(float4*)(Asn + m * AST + e4) = h;
                    int k = sm_k + q * 8, f4 = 4 * sm_e2;
                    float4 wv = pb[q];
                    wv.x = tf32r(wv.x); wv.y = tf32r(wv.y);
                    wv.z = tf32r(wv.z); wv.w = tf32r(wv.w);
                    *(float4*)(Bsn + k * BST + f4) = wv;
                }
            }
            __syncthreads();
            buf ^= 1;
        }

        // ---- epilogue accumulate: v += relu(acc + b2) * W3 ----
#pragma unroll
        for (int mt = 0; mt < 2; mt++)
#pragma unroll
            for (int nt = 0; nt < 8; nt++)
#pragma unroll
                for (int j = 0; j < 4; j++) {
                    int nl = wn * 64 + nt * 8 + tig * 2 + (j & 1);
                    float2 p = bw[n0 + nl];
                    v[mt * 2 + (j >> 1)] +=
                        fmaxf(acc[mt][nt][j] + p.x, 0.f) * p.y;
                }
    }

    // reduce over tig (quad lanes), combine the two n-warps via smem
#pragma unroll
    for (int r = 0; r < 4; r++) {
        v[r] += __shfl_xor_sync(0xffffffffu, v[r], 1);
        v[r] += __shfl_xor_sync(0xffffffffu, v[r], 2);
    }
    if (tig == 0) {
#pragma unroll
        for (int mt = 0; mt < 2; mt++)
#pragma unroll
            for (int half = 0; half < 2; half++)
                vred[wn * 128 + wm * 32 + mt * 16 + half * 8 + g] =
                    v[mt * 2 + half];
    }
    __syncthreads();

    if (tid < TILE_M) {
        float sum = vred[tid] + vred[128 + tid];
        float sc = __ldg(psc), bi = __ldg(pbi), b3v = __ldg(b3);
        float z = sc * (sum + b3v) + bi;
        out[(size_t)b * ROWS_PER_B + t0 + tid] = 1.f / (1.f + expf(-z));
    }
}

// ---------------------------------------------------------------------------
extern "C" void kernel_launch(void* const* d_in, const int* in_sizes, int n_in,
                              void* d_out, int out_size) {
    const float* node = (const float*)d_in[0];
    const float* pair = (const float*)d_in[1];
    const float* W1n  = (const float*)d_in[2];
    const float* W1p  = (const float*)d_in[3];
    const float* b1   = (const float*)d_in[4];
    const float* W2   = (const float*)d_in[5];
    const float* b2   = (const float*)d_in[6];
    const float* W3   = (const float*)d_in[7];
    const float* b3   = (const float*)d_in[8];
    const float* sc   = (const float*)d_in[9];
    const float* bi   = (const float*)d_in[10];
    float* out = (float*)d_out;

    cudaFuncSetAttribute(k_main, cudaFuncAttributeMaxDynamicSharedMemorySize,
                         SM_TOTAL);

    k_node<<<NB * NNODE, NH>>>(node, W1n);
    k_pair<<<NB * NJK, NH>>>(pair, W1p, b1);

    dim3 grid(ROWS_PER_B / TILE_M, NB);   // 500 x 2 = 1000 CTAs
    k_main<<<grid, 256, SM_TOTAL>>>(W2, b2, W3, b3, sc, bi, out);
}

// round 6
// speedup vs baseline: 3.6862x; 1.3352x over previous
#include <cuda_runtime.h>
#include <cstdint>

#define NB 2
#define ND 8
#define NNODE 40
#define NH 128
#define HID 512
#define NJK (NNODE * NNODE)        // 1600
#define NJT 13                     // ceil(1600/128) jk-tiles
#define TILE_M 128
#define TILE_N 256                 // N-slice per pass
#define NPASS (HID / TILE_N)       // 2
#define KCH 32
#define NCHUNKS (HID / KCH)        // 16

#define AST 36                     // A smem row stride (floats)
#define BST 264                    // B smem row stride (floats)

// -------- device scratch --------
__device__ float g_A[NB * NNODE * HID];   // hn        [b][i][k]
__device__ float g_C[NB * NJK * HID];     // hp + b1   [b][jk][k]

// -------- dynamic smem layout (bytes) --------
#define SM_COFF   0                        // 128 ints
#define SM_SA     512                      // 512 floats (gA row)
#define SM_BW     2560                     // 512 float2 (b2, W3)
#define SM_VRED   6656                     // 256 floats
#define SM_ST0    7680
#define STG_SZ    52224                    // A 18432 + B 33792
#define SM_BOFF   18432                    // B offset within stage
#define SM_TOTAL  (SM_ST0 + 3 * STG_SZ)   // 164352

__device__ __forceinline__ uint32_t smem_u32(const void* p) {
    uint32_t a;
    asm("{ .reg .u64 t; cvta.to.shared.u64 t, %1; cvt.u32.u64 %0, t; }" : "=r"(a) : "l"(p));
    return a;
}
__device__ __forceinline__ float tf32r(float x) {
    float y;
    asm("cvt.rna.tf32.f32 %0, %1;" : "=f"(y) : "f"(x));
    return y;
}
__device__ __forceinline__ void cp16(uint32_t dst, const void* src) {
    asm volatile("cp.async.cg.shared.global [%0], [%1], 16;" :: "r"(dst), "l"(src) : "memory");
}
__device__ __forceinline__ void cp_commit() {
    asm volatile("cp.async.commit_group;" ::: "memory");
}
__device__ __forceinline__ void cp_wait1() {
    asm volatile("cp.async.wait_group 1;" ::: "memory");
}
__device__ __forceinline__ void cp_wait0() {
    asm volatile("cp.async.wait_group 0;" ::: "memory");
}
__device__ __forceinline__ void mma_tf32(float* d, const uint32_t* a,
                                         uint32_t b0, uint32_t b1) {
    asm volatile(
        "mma.sync.aligned.m16n8k8.row.col.f32.tf32.tf32.f32 "
        "{%0,%1,%2,%3}, {%4,%5,%6,%7}, {%8,%9}, {%0,%1,%2,%3};"
        : "+f"(d[0]), "+f"(d[1]), "+f"(d[2]), "+f"(d[3])
        : "r"(a[0]), "r"(a[1]), "r"(a[2]), "r"(a[3]), "r"(b0), "r"(b1));
}

// ---------------------------------------------------------------------------
// Kernel A: nf = max_d(node_feature); g_A[b][i][:] = nf @ W1n
// ---------------------------------------------------------------------------
__global__ void k_node(const float* __restrict__ nfin,
                       const float* __restrict__ W1n) {
    __shared__ float s[NH];
    int bi = blockIdx.x;
    int t  = threadIdx.x;
    int b  = bi / NNODE, i = bi % NNODE;

    const float* base = nfin + (((size_t)b * ND) * NNODE + i) * NH + t;
    float m = base[0];
#pragma unroll
    for (int d = 1; d < ND; d++)
        m = fmaxf(m, base[(size_t)d * NNODE * NH]);
    s[t] = m;
    __syncthreads();

    float a0 = 0.f, a1 = 0.f, a2 = 0.f, a3 = 0.f;
    const float* w = W1n + t * 4;
#pragma unroll 8
    for (int h = 0; h < NH; h++) {
        float4 wv = *(const float4*)(w + (size_t)h * HID);
        float x = s[h];
        a0 = fmaf(x, wv.x, a0);
        a1 = fmaf(x, wv.y, a1);
        a2 = fmaf(x, wv.z, a2);
        a3 = fmaf(x, wv.w, a3);
    }
    float4 o = {a0, a1, a2, a3};
    *(float4*)(g_A + (size_t)bi * HID + t * 4) = o;
}

// ---------------------------------------------------------------------------
// Kernel B: pf = max_d(pairwise_feature); g_C[b][jk][:] = pf @ W1p + b1
// ---------------------------------------------------------------------------
__global__ void k_pair(const float* __restrict__ pfin,
                       const float* __restrict__ W1p,
                       const float* __restrict__ b1) {
    __shared__ float s[NH];
    int r = blockIdx.x;
    int t = threadIdx.x;
    int b = r / NJK, jk = r % NJK;

    const float* base = pfin + (((size_t)b * ND) * NJK + jk) * NH + t;
    float m = base[0];
#pragma unroll
    for (int d = 1; d < ND; d++)
        m = fmaxf(m, base[(size_t)d * NJK * NH]);
    s[t] = m;
    __syncthreads();

    float4 bv = *(const float4*)(b1 + t * 4);
    float a0 = bv.x, a1 = bv.y, a2 = bv.z, a3 = bv.w;
    const float* w = W1p + t * 4;
#pragma unroll 8
    for (int h = 0; h < NH; h++) {
        float4 wv = *(const float4*)(w + (size_t)h * HID);
        float x = s[h];
        a0 = fmaf(x, wv.x, a0);
        a1 = fmaf(x, wv.y, a1);
        a2 = fmaf(x, wv.z, a2);
        a3 = fmaf(x, wv.w, a3);
    }
    float4 o = {a0, a1, a2, a3};
    *(float4*)(g_C + (size_t)r * HID + t * 4) = o;
}

// ---------------------------------------------------------------------------
// Kernel C: mma.sync tf32 GEMM, cp.async 3-stage, fused MLP tail.
//   Grid (jt, i, b): all 128 rows share node row i ->
//   A = relu(C_rows + broadcast(gA_row)) built at fragment-load time.
//   8 warps: wm = wid&3 (M 32-blocks), wn = wid>>2 (N 128-halves).
// ---------------------------------------------------------------------------
__global__ __launch_bounds__(256, 1)
void k_main(const float* __restrict__ W2, const float* __restrict__ b2,
            const float* __restrict__ W3, const float* __restrict__ b3,
            const float* __restrict__ psc, const float* __restrict__ pbi,
            float* __restrict__ out) {
    extern __shared__ char smem[];
    int*    coff = (int*)(smem + SM_COFF);
    float*  sA   = (float*)(smem + SM_SA);
    float2* bw   = (float2*)(smem + SM_BW);
    float*  vred = (float*)(smem + SM_VRED);

    const uint32_t sbase = smem_u32(smem);
    const int tid  = threadIdx.x;
    const int wid  = tid >> 5, lane = tid & 31;
    const int g    = lane >> 2, tig = lane & 3;
    const int wm   = wid & 3, wn = wid >> 2;
    const int b    = blockIdx.z;
    const int i    = blockIdx.y;
    const int jk0  = blockIdx.x * TILE_M;

    // per-CTA setup
    if (tid < TILE_M) {
        int jk = jk0 + tid;
        if (jk > NJK - 1) jk = NJK - 1;
        coff[tid] = (b * NJK + jk) * HID;
    }
    {
        const float* ga = g_A + ((size_t)b * NNODE + i) * HID;
        for (int t = tid; t < HID; t += 256) sA[t] = ga[t];
        for (int n = tid; n < HID; n += 256) bw[n] = make_float2(b2[n], W3[n]);
    }
    __syncthreads();

    // staging descriptors (constant per thread)
    const int sm_m = tid >> 3, sm_e = tid & 7;     // A granules: 4x (rows sm_m+32q)
    const int sm_k = tid >> 6, sm_e2 = tid & 63;   // B granules: 8x (rows sm_k+4q)
    const float* csrc[4];
#pragma unroll
    for (int q = 0; q < 4; q++)
        csrc[q] = g_C + coff[sm_m + 32 * q] + 4 * sm_e;
    uint32_t adst[4], bdst[4 * 2];
#pragma unroll
    for (int q = 0; q < 4; q++)
        adst[q] = (uint32_t)(((sm_m + 32 * q) * AST + 4 * sm_e) * 4);
#pragma unroll
    for (int q = 0; q < 8; q++)
        bdst[q] = (uint32_t)(SM_BOFF + ((sm_k + 4 * q) * BST + 4 * sm_e2) * 4);

    uint32_t stg[3];
#pragma unroll
    for (int s = 0; s < 3; s++) stg[s] = sbase + SM_ST0 + s * STG_SZ;

    float v[4] = {0.f, 0.f, 0.f, 0.f};

    for (int np = 0; np < NPASS; np++) {
        const int n0 = np * TILE_N;
        const float* bbase = W2 + n0 + 4 * sm_e2;

        float acc[2][16][4];
#pragma unroll
        for (int mt = 0; mt < 2; mt++)
#pragma unroll
            for (int nt = 0; nt < 16; nt++)
#pragma unroll
                for (int j = 0; j < 4; j++) acc[mt][nt][j] = 0.f;

        // prologue: issue chunks 0, 1
#pragma unroll
        for (int c = 0; c < 2; c++) {
            const int kc = c * KCH;
            const uint32_t st = stg[c];
#pragma unroll
            for (int q = 0; q < 4; q++) cp16(st + adst[q], csrc[q] + kc);
#pragma unroll
            for (int q = 0; q < 8; q++)
                cp16(st + bdst[q], bbase + (size_t)(kc + sm_k + 4 * q) * HID);
            cp_commit();
        }

        for (int c = 0; c < NCHUNKS; c++) {
            if (c < NCHUNKS - 1) cp_wait1(); else cp_wait0();
            __syncthreads();

            // issue chunk c+2 into stage (c+2)%3
            if (c + 2 < NCHUNKS) {
                const int kc = (c + 2) * KCH;
                const uint32_t st = stg[(c + 2) % 3];
#pragma unroll
                for (int q = 0; q < 4; q++) cp16(st + adst[q], csrc[q] + kc);
#pragma unroll
                for (int q = 0; q < 8; q++)
                    cp16(st + bdst[q], bbase + (size_t)(kc + sm_k + 4 * q) * HID);
                cp_commit();
            }

            // compute chunk c from stage c%3
            const char* sp = smem + SM_ST0 + (c % 3) * STG_SZ;
            const float* As = (const float*)sp;
            const float* Bs = (const float*)(sp + SM_BOFF);
            const int kb0 = c * KCH;
#pragma unroll
            for (int ks = 0; ks < 4; ks++) {
                const int kb = ks * 8 + tig;
                const float a1 = sA[kb0 + kb];
                const float a2 = sA[kb0 + kb + 4];
                uint32_t afr[2][4];
#pragma unroll
                for (int mt = 0; mt < 2; mt++) {
                    const int r0 = wm * 32 + mt * 16 + g;
                    afr[mt][0] = __float_as_uint(tf32r(fmaxf(As[r0 * AST + kb] + a1, 0.f)));
                    afr[mt][1] = __float_as_uint(tf32r(fmaxf(As[(r0 + 8) * AST + kb] + a1, 0.f)));
                    afr[mt][2] = __float_as_uint(tf32r(fmaxf(As[r0 * AST + kb + 4] + a2, 0.f)));
                    afr[mt][3] = __float_as_uint(tf32r(fmaxf(As[(r0 + 8) * AST + kb + 4] + a2, 0.f)));
                }
#pragma unroll
                for (int nt = 0; nt < 16; nt++) {
                    const int bc = wn * 128 + nt * 8 + g;
                    uint32_t b0 = __float_as_uint(Bs[(ks * 8 + tig) * BST + bc]);
                    uint32_t b1 = __float_as_uint(Bs[(ks * 8 + tig + 4) * BST + bc]);
                    mma_tf32(acc[0][nt], afr[0], b0, b1);
                    mma_tf32(acc[1][nt], afr[1], b0, b1);
                }
            }
        }
        __syncthreads();   // stage reuse safety across passes

        // epilogue accumulate: v += relu(acc + b2) * W3
#pragma unroll
        for (int mt = 0; mt < 2; mt++)
#pragma unroll
            for (int nt = 0; nt < 16; nt++)
#pragma unroll
                for (int j = 0; j < 4; j++) {
                    const int nl = wn * 128 + nt * 8 + tig * 2 + (j & 1);
                    float2 p = bw[n0 + nl];
                    v[mt * 2 + (j >> 1)] += fmaxf(acc[mt][nt][j] + p.x, 0.f) * p.y;
                }
    }

    // reduce over quad lanes, combine the two n-warps via smem
#pragma unroll
    for (int r = 0; r < 4; r++) {
        v[r] += __shfl_xor_sync(0xffffffffu, v[r], 1);
        v[r] += __shfl_xor_sync(0xffffffffu, v[r], 2);
    }
    if (tig == 0) {
#pragma unroll
        for (int mt = 0; mt < 2; mt++)
#pragma unroll
            for (int half = 0; half < 2; half++)
                vred[wn * 128 + wm * 32 + mt * 16 + half * 8 + g] = v[mt * 2 + half];
    }
    __syncthreads();

    if (tid < TILE_M && jk0 + tid < NJK) {
        float sum = vred[tid] + vred[128 + tid];
        float sc = __ldg(psc), bi2 = __ldg(pbi), b3v = __ldg(b3);
        float z = sc * (sum + b3v) + bi2;
        out[((size_t)b * NNODE + i) * NJK + jk0 + tid] = 1.f / (1.f + expf(-z));
    }
}

// ---------------------------------------------------------------------------
extern "C" void kernel_launch(void* const* d_in, const int* in_sizes, int n_in,
                              void* d_out, int out_size) {
    const float* node = (const float*)d_in[0];
    const float* pair = (const float*)d_in[1];
    const float* W1n  = (const float*)d_in[2];
    const float* W1p  = (const float*)d_in[3];
    const float* b1   = (const float*)d_in[4];
    const float* W2   = (const float*)d_in[5];
    const float* b2   = (const float*)d_in[6];
    const float* W3   = (const float*)d_in[7];
    const float* b3   = (const float*)d_in[8];
    const float* sc   = (const float*)d_in[9];
    const float* bi   = (const float*)d_in[10];
    float* out = (float*)d_out;

    cudaFuncSetAttribute(k_main, cudaFuncAttributeMaxDynamicSharedMemorySize,
                         SM_TOTAL);

    k_node<<<NB * NNODE, NH>>>(node, W1n);
    k_pair<<<NB * NJK, NH>>>(pair, W1p, b1);

    dim3 grid(NJT, NNODE, NB);   // 13 x 40 x 2 = 1040 CTAs
    k_main<<<grid, 256, SM_TOTAL>>>(W2, b2, W3, b3, sc, bi, out);
}

// round 7
// speedup vs baseline: 3.6893x; 1.0009x over previous
#include <cuda_runtime.h>
#include <cuda_fp16.h>
#include <cstdint>

#define NB 2
#define ND 8
#define NNODE 40
#define NH 128
#define HID 512
#define NJK (NNODE * NNODE)        // 1600
#define NJT 13                     // ceil(1600/128) jk-tiles
#define TILE_M 128
#define TILE_N 256
#define NPASS (HID / TILE_N)       // 2
#define KCH 32
#define NCHUNKS (HID / KCH)        // 16
#define NSTG 4

#define AST 40                     // A smem row stride (f32 words)
#define BSTW 20                    // B smem row stride (b32 words = 40 halfs)

// -------- device scratch --------
__device__ float  g_A[NB * NNODE * HID];   // hn        [b][i][k]
__device__ float  g_C[NB * NJK * HID];     // hp + b1   [b][jk][k]
__device__ __half g_W2h[HID * HID];        // W2^T      [n][k] half

// -------- dynamic smem layout (bytes) --------
#define SM_COFF   0                        // 128 ints
#define SM_SA     512                      // 512 f32 (gA row)
#define SM_BW     2560                     // 512 float2 (b2, W3)
#define SM_VRED   6656                     // 256 f32
#define SM_ST0    7680
#define SM_BOFF   20480                    // B offset within stage (A = 128*40*4)
#define STG_SZ    40960                    // A 20480 + B 20480
#define SM_TOTAL  (SM_ST0 + NSTG * STG_SZ)  // 171520

__device__ __forceinline__ uint32_t smem_u32(const void* p) {
    uint32_t a;
    asm("{ .reg .u64 t; cvta.to.shared.u64 t, %1; cvt.u32.u64 %0, t; }" : "=r"(a) : "l"(p));
    return a;
}
__device__ __forceinline__ uint32_t h2pack(float lo, float hi) {
    uint32_t r;
    asm("cvt.rn.f16x2.f32 %0, %1, %2;" : "=r"(r) : "f"(hi), "f"(lo));
    return r;
}
__device__ __forceinline__ void cp16(uint32_t dst, const void* src) {
    asm volatile("cp.async.cg.shared.global [%0], [%1], 16;" :: "r"(dst), "l"(src) : "memory");
}
__device__ __forceinline__ void cp_commit() {
    asm volatile("cp.async.commit_group;" ::: "memory");
}
template <int N>
__device__ __forceinline__ void cp_waitg() {
    asm volatile("cp.async.wait_group %0;" :: "n"(N) : "memory");
}
__device__ __forceinline__ void mma_f16(float* d, const uint32_t* a,
                                        uint32_t b0, uint32_t b1) {
    asm volatile(
        "mma.sync.aligned.m16n8k16.row.col.f32.f16.f16.f32 "
        "{%0,%1,%2,%3}, {%4,%5,%6,%7}, {%8,%9}, {%0,%1,%2,%3};"
        : "+f"(d[0]), "+f"(d[1]), "+f"(d[2]), "+f"(d[3])
        : "r"(a[0]), "r"(a[1]), "r"(a[2]), "r"(a[3]), "r"(b0), "r"(b1));
}

// ---------------------------------------------------------------------------
// Kernel A: nf = max_d(node_feature); g_A[b][i][:] = nf @ W1n
// grid (NB*NNODE, 4) x 128 threads — each CTA covers a 128-col quarter.
// ---------------------------------------------------------------------------
__global__ void k_node(const float* __restrict__ nfin,
                       const float* __restrict__ W1n) {
    __shared__ float s[NH];
    __shared__ float4 red[4][32];
    int bi = blockIdx.x, nq = blockIdx.y;
    int b = bi / NNODE, i = bi % NNODE;
    int t = threadIdx.x;

    const float* base = nfin + (((size_t)b * ND) * NNODE + i) * NH + t;
    float m = base[0];
#pragma unroll
    for (int d = 1; d < ND; d++)
        m = fmaxf(m, base[(size_t)d * NNODE * NH]);
    s[t] = m;
    __syncthreads();

    int hq = t >> 5, c = t & 31;
    int n = nq * 128 + c * 4;
    float a0 = 0.f, a1 = 0.f, a2 = 0.f, a3 = 0.f;
#pragma unroll 8
    for (int h = hq * 32; h < hq * 32 + 32; h++) {
        float4 wv = *(const float4*)(W1n + (size_t)h * HID + n);
        float x = s[h];
        a0 = fmaf(x, wv.x, a0);
        a1 = fmaf(x, wv.y, a1);
        a2 = fmaf(x, wv.z, a2);
        a3 = fmaf(x, wv.w, a3);
    }
    red[hq][c] = make_float4(a0, a1, a2, a3);
    __syncthreads();
    if (hq == 0) {
        float4 r0 = red[0][c], r1 = red[1][c], r2 = red[2][c], r3 = red[3][c];
        float4 o;
        o.x = r0.x + r1.x + r2.x + r3.x;
        o.y = r0.y + r1.y + r2.y + r3.y;
        o.z = r0.z + r1.z + r2.z + r3.z;
        o.w = r0.w + r1.w + r2.w + r3.w;
        *(float4*)(g_A + (size_t)bi * HID + n) = o;
    }
}

// ---------------------------------------------------------------------------
// Kernel B: pf = max_d(pairwise_feature); g_C[b][jk][:] = pf @ W1p + b1
// grid NB*NJK/8 CTAs x 256 threads: 8 jk rows per CTA, W1p shared via L2.
// ---------------------------------------------------------------------------
__global__ void k_pair(const float* __restrict__ pfin,
                       const float* __restrict__ W1p,
                       const float* __restrict__ b1) {
    __shared__ float sP[8][NH];
    int row0 = blockIdx.x * 8;       // global row over NB*NJK
    int b = row0 / NJK, jk0 = row0 % NJK;
    int t = threadIdx.x;

    for (int e = t; e < 8 * NH; e += 256) {
        int r = e >> 7, h = e & 127;
        const float* base = pfin + (((size_t)b * ND) * NJK + jk0 + r) * NH + h;
        float m = base[0];
#pragma unroll
        for (int d = 1; d < ND; d++)
            m = fmaxf(m, base[(size_t)d * NJK * NH]);
        sP[r][h] = m;
    }
    __syncthreads();

    int n = t * 2;
    float2 bv = *(const float2*)(b1 + n);
    float acc[8][2];
#pragma unroll
    for (int r = 0; r < 8; r++) { acc[r][0] = bv.x; acc[r][1] = bv.y; }

#pragma unroll 4
    for (int k = 0; k < NH; k++) {
        float2 w = *(const float2*)(W1p + (size_t)k * HID + n);
#pragma unroll
        for (int r = 0; r < 8; r++) {
            float x = sP[r][k];
            acc[r][0] = fmaf(x, w.x, acc[r][0]);
            acc[r][1] = fmaf(x, w.y, acc[r][1]);
        }
    }
#pragma unroll
    for (int r = 0; r < 8; r++)
        *(float2*)(g_C + ((size_t)b * NJK + jk0 + r) * HID + n) =
            make_float2(acc[r][0], acc[r][1]);
}

// ---------------------------------------------------------------------------
// Kernel T: g_W2h[n][k] = half(W2[k][n])
// ---------------------------------------------------------------------------
__global__ void k_w2h(const float* __restrict__ W2) {
    __shared__ float t[32][33];
    int n0 = blockIdx.x * 32, k0 = blockIdx.y * 32;
    int tx = threadIdx.x, ty = threadIdx.y;   // 32 x 8
#pragma unroll
    for (int r = ty; r < 32; r += 8)
        t[r][tx] = W2[(size_t)(k0 + r) * HID + n0 + tx];
    __syncthreads();
#pragma unroll
    for (int r = ty; r < 32; r += 8)
        g_W2h[(size_t)(n0 + r) * HID + k0 + tx] = __float2half(t[tx][r]);
}

// ---------------------------------------------------------------------------
// Kernel C: fp16 mma.sync GEMM (m16n8k16), 4-stage cp.async, fused MLP tail.
//   Grid (jt, i, b): 128 jk rows share node row i.
//   A smem f32 (relu-add-cvt at fragment build); B smem half [n][k].
// ---------------------------------------------------------------------------
__global__ __launch_bounds__(256, 1)
void k_main(const float* __restrict__ b2, const float* __restrict__ W3,
            const float* __restrict__ b3, const float* __restrict__ psc,
            const float* __restrict__ pbi, float* __restrict__ out) {
    extern __shared__ char smem[];
    int*    coff = (int*)(smem + SM_COFF);
    float*  sA   = (float*)(smem + SM_SA);
    float2* bw   = (float2*)(smem + SM_BW);
    float*  vred = (float*)(smem + SM_VRED);

    const uint32_t sbase = smem_u32(smem);
    const int tid = threadIdx.x;
    const int wid = tid >> 5, lane = tid & 31;
    const int g = lane >> 2, tig = lane & 3;
    const int wm = wid & 3, wn = wid >> 2;
    const int b = blockIdx.z;
    const int i = blockIdx.y;
    const int jk0 = blockIdx.x * TILE_M;

    if (tid < TILE_M) {
        int jk = jk0 + tid;
        if (jk > NJK - 1) jk = NJK - 1;
        coff[tid] = (b * NJK + jk) * HID;
    }
    {
        const float* ga = g_A + ((size_t)b * NNODE + i) * HID;
        for (int t = tid; t < HID; t += 256) sA[t] = ga[t];
        for (int n = tid; n < HID; n += 256) bw[n] = make_float2(b2[n], W3[n]);
    }
    __syncthreads();

    // staging descriptors
    const int sm_m = tid >> 3, sm_e = tid & 7;   // A: 4x rows (sm_m + 32q), 16B units
    const int sm_n = tid >> 2, sm_f = tid & 3;   // B: 4x rows (sm_n + 64q), 16B units
    const float* csrc[4];
#pragma unroll
    for (int q = 0; q < 4; q++)
        csrc[q] = g_C + coff[sm_m + 32 * q] + 4 * sm_e;
    uint32_t adst[4], bdst[4];
#pragma unroll
    for (int q = 0; q < 4; q++) {
        adst[q] = (uint32_t)((sm_m + 32 * q) * (AST * 4) + sm_e * 16);
        bdst[q] = (uint32_t)(SM_BOFF + (sm_n + 64 * q) * (BSTW * 4) + sm_f * 16);
    }
    uint32_t stg[NSTG];
#pragma unroll
    for (int s = 0; s < NSTG; s++) stg[s] = sbase + SM_ST0 + s * STG_SZ;

    float v[4] = {0.f, 0.f, 0.f, 0.f};

    for (int np = 0; np < NPASS; np++) {
        const int n0 = np * TILE_N;
        const __half* bbase = g_W2h + (size_t)n0 * HID + 8 * sm_f;

        float acc[2][16][4];
#pragma unroll
        for (int mt = 0; mt < 2; mt++)
#pragma unroll
            for (int nt = 0; nt < 16; nt++)
#pragma unroll
                for (int j = 0; j < 4; j++) acc[mt][nt][j] = 0.f;

        // prologue: issue chunks 0..2
#pragma unroll
        for (int c = 0; c < NSTG - 1; c++) {
            const int kc = c * KCH;
            const uint32_t st = stg[c];
#pragma unroll
            for (int q = 0; q < 4; q++) cp16(st + adst[q], csrc[q] + kc);
#pragma unroll
            for (int q = 0; q < 4; q++)
                cp16(st + bdst[q], bbase + (size_t)(sm_n + 64 * q) * HID + kc);
            cp_commit();
        }

        for (int c = 0; c < NCHUNKS; c++) {
            if (c < NCHUNKS - 2) cp_waitg<2>();
            else if (c == NCHUNKS - 2) cp_waitg<1>();
            else cp_waitg<0>();
            __syncthreads();

            if (c + NSTG - 1 < NCHUNKS) {
                const int kc = (c + NSTG - 1) * KCH;
                const uint32_t st = stg[(c + NSTG - 1) % NSTG];
#pragma unroll
                for (int q = 0; q < 4; q++) cp16(st + adst[q], csrc[q] + kc);
#pragma unroll
                for (int q = 0; q < 4; q++)
                    cp16(st + bdst[q], bbase + (size_t)(sm_n + 64 * q) * HID + kc);
                cp_commit();
            }

            const char* sp = smem + SM_ST0 + (c % NSTG) * STG_SZ;
            const float* As = (const float*)sp;
            const uint32_t* Bs = (const uint32_t*)(sp + SM_BOFF);
            const int kb0 = c * KCH;

#pragma unroll
            for (int kst = 0; kst < 2; kst++) {
                const int kb = kst * 16 + 2 * tig;
                const float2 av0 = *(const float2*)(sA + kb0 + kb);
                const float2 av1 = *(const float2*)(sA + kb0 + kb + 8);
                uint32_t afr[2][4];
#pragma unroll
                for (int mt = 0; mt < 2; mt++) {
                    const float* Ar0 = As + (wm * 32 + mt * 16 + g) * AST + kb;
                    const float* Ar1 = Ar0 + 8 * AST;
                    float2 c00 = *(const float2*)(Ar0);
                    float2 c01 = *(const float2*)(Ar0 + 8);
                    float2 c10 = *(const float2*)(Ar1);
                    float2 c11 = *(const float2*)(Ar1 + 8);
                    afr[mt][0] = h2pack(fmaxf(c00.x + av0.x, 0.f), fmaxf(c00.y + av0.y, 0.f));
                    afr[mt][1] = h2pack(fmaxf(c10.x + av0.x, 0.f), fmaxf(c10.y + av0.y, 0.f));
                    afr[mt][2] = h2pack(fmaxf(c01.x + av1.x, 0.f), fmaxf(c01.y + av1.y, 0.f));
                    afr[mt][3] = h2pack(fmaxf(c11.x + av1.x, 0.f), fmaxf(c11.y + av1.y, 0.f));
                }
#pragma unroll
                for (int nt = 0; nt < 16; nt++) {
                    const int bc = wn * 128 + nt * 8 + g;
                    const uint32_t* Bw = Bs + bc * BSTW + kst * 8;
                    uint32_t b0 = Bw[tig];
                    uint32_t b1 = Bw[tig + 4];
                    mma_f16(acc[0][nt], afr[0], b0, b1);
                    mma_f16(acc[1][nt], afr[1], b0, b1);
                }
            }
        }
        __syncthreads();

        // epilogue accumulate: v += relu(acc + b2) * W3
#pragma unroll
        for (int mt = 0; mt < 2; mt++)
#pragma unroll
            for (int nt = 0; nt < 16; nt++)
#pragma unroll
                for (int j = 0; j < 4; j++) {
                    const int nl = wn * 128 + nt * 8 + tig * 2 + (j & 1);
                    float2 p = bw[n0 + nl];
                    v[mt * 2 + (j >> 1)] += fmaxf(acc[mt][nt][j] + p.x, 0.f) * p.y;
                }
    }

    // reduce over quad lanes, combine n-warps via smem
#pragma unroll
    for (int r = 0; r < 4; r++) {
        v[r] += __shfl_xor_sync(0xffffffffu, v[r], 1);
        v[r] += __shfl_xor_sync(0xffffffffu, v[r], 2);
    }
    if (tig == 0) {
#pragma unroll
        for (int mt = 0; mt < 2; mt++)
#pragma unroll
            for (int half = 0; half < 2; half++)
                vred[wn * 128 + wm * 32 + mt * 16 + half * 8 + g] = v[mt * 2 + half];
    }
    __syncthreads();

    if (tid < TILE_M && jk0 + tid < NJK) {
        float sum = vred[tid] + vred[128 + tid];
        float sc = __ldg(psc), bi2 = __ldg(pbi), b3v = __ldg(b3);
        float z = sc * (sum + b3v) + bi2;
        out[((size_t)b * NNODE + i) * NJK + jk0 + tid] = 1.f / (1.f + expf(-z));
    }
}

// ---------------------------------------------------------------------------
extern "C" void kernel_launch(void* const* d_in, const int* in_sizes, int n_in,
                              void* d_out, int out_size) {
    const float* node = (const float*)d_in[0];
    const float* pair = (const float*)d_in[1];
    const float* W1n  = (const float*)d_in[2];
    const float* W1p  = (const float*)d_in[3];
    const float* b1   = (const float*)d_in[4];
    const float* W2   = (const float*)d_in[5];
    const float* b2   = (const float*)d_in[6];
    const float* W3   = (const float*)d_in[7];
    const float* b3   = (const float*)d_in[8];
    const float* sc   = (const float*)d_in[9];
    const float* bi   = (const float*)d_in[10];
    float* out = (float*)d_out;

    cudaFuncSetAttribute(k_main, cudaFuncAttributeMaxDynamicSharedMemorySize,
                         SM_TOTAL);

    k_node<<<dim3(NB * NNODE, 4), NH>>>(node, W1n);
    k_pair<<<NB * NJK / 8, 256>>>(pair, W1p, b1);
    k_w2h<<<dim3(16, 16), dim3(32, 8)>>>(W2);

    dim3 grid(NJT, NNODE, NB);   // 13 x 40 x 2 = 1040 CTAs
    k_main<<<grid, 256, SM_TOTAL>>>(b2, W3, b3, sc, bi, out);
}

// round 9
// speedup vs baseline: 5.0665x; 1.3733x over previous
#include <cuda_runtime.h>
#include <cuda_fp16.h>
#include <cstdint>

#define NB 2
#define ND 8
#define NNODE 40
#define NH 128
#define HID 512
#define NJK (NNODE * NNODE)        // 1600
#define NJT 13                     // ceil(1600/128)
#define TILE_M 128
#define TILE_N 256
#define NPASS (HID / TILE_N)       // 2
#define KCH 32
#define NCHUNKS (HID / KCH)        // 16
#define NSTG 3
#define THREADS 512

#define CST 36                     // C stage row stride (f32 words)
#define BSTW 20                    // B stage row stride (b32 words = 40 halfs)
#define AHB 80                     // A-half row stride (bytes) = 40 halfs

// -------- device scratch --------
__device__ float  g_A[NB * NNODE * HID];   // hn        [b][i][k]
__device__ float  g_C[NB * NJK * HID];     // hp + b1   [b][jk][k]
__device__ __half g_W2h[HID * HID];        // W2^T      [n][k] half

// -------- dynamic smem layout (bytes) --------
#define SM_COFF   0                        // 128 ints
#define SM_SA     512                      // 512 f32
#define SM_BW     2560                     // 512 float2 (b2, W3)
#define SM_VRED   6656                     // 4*128 f32
#define SM_AH     8704                     // 128*80 = 10240 (half tile)
#define SM_ST0    19456                    // stages, 1024-aligned
#define SM_BOFF   18432                    // B offset within stage (C = 128*144)
#define STG_SZ    38912                    // C 18432 + B 20480
#define SM_TOTAL  (SM_ST0 + NSTG * STG_SZ) // 136192

__device__ __forceinline__ uint32_t smem_u32(const void* p) {
    uint32_t a;
    asm("{ .reg .u64 t; cvta.to.shared.u64 t, %1; cvt.u32.u64 %0, t; }" : "=r"(a) : "l"(p));
    return a;
}
__device__ __forceinline__ uint32_t h2pack(float lo, float hi) {
    uint32_t r;
    asm("cvt.rn.f16x2.f32 %0, %1, %2;" : "=r"(r) : "f"(hi), "f"(lo));
    return r;
}
__device__ __forceinline__ void cp16(uint32_t dst, const void* src) {
    asm volatile("cp.async.cg.shared.global [%0], [%1], 16;" :: "r"(dst), "l"(src) : "memory");
}
__device__ __forceinline__ void cp_commit() {
    asm volatile("cp.async.commit_group;" ::: "memory");
}
template <int N>
__device__ __forceinline__ void cp_waitg() {
    asm volatile("cp.async.wait_group %0;" :: "n"(N) : "memory");
}
__device__ __forceinline__ void ldmx4(uint32_t* r, uint32_t addr) {
    asm volatile("ldmatrix.sync.aligned.m8n8.x4.shared.b16 {%0,%1,%2,%3}, [%4];"
                 : "=r"(r[0]), "=r"(r[1]), "=r"(r[2]), "=r"(r[3]) : "r"(addr));
}
__device__ __forceinline__ void mma_f16(float* d, const uint32_t* a,
                                        uint32_t b0, uint32_t b1) {
    asm volatile(
        "mma.sync.aligned.m16n8k16.row.col.f32.f16.f16.f32 "
        "{%0,%1,%2,%3}, {%4,%5,%6,%7}, {%8,%9}, {%0,%1,%2,%3};"
        : "+f"(d[0]), "+f"(d[1]), "+f"(d[2]), "+f"(d[3])
        : "r"(a[0]), "r"(a[1]), "r"(a[2]), "r"(a[3]), "r"(b0), "r"(b1));
}

// ---------------------------------------------------------------------------
// Kernel A: nf = max_d(node_feature); g_A[b][i][:] = nf @ W1n
// ---------------------------------------------------------------------------
__global__ void k_node(const float* __restrict__ nfin,
                       const float* __restrict__ W1n) {
    __shared__ float s[NH];
    __shared__ float4 red[4][32];
    int bi = blockIdx.x, nq = blockIdx.y;
    int b = bi / NNODE, i = bi % NNODE;
    int t = threadIdx.x;

    const float* base = nfin + (((size_t)b * ND) * NNODE + i) * NH + t;
    float m = base[0];
#pragma unroll
    for (int d = 1; d < ND; d++)
        m = fmaxf(m, base[(size_t)d * NNODE * NH]);
    s[t] = m;
    __syncthreads();

    int hq = t >> 5, c = t & 31;
    int n = nq * 128 + c * 4;
    float a0 = 0.f, a1 = 0.f, a2 = 0.f, a3 = 0.f;
#pragma unroll 8
    for (int h = hq * 32; h < hq * 32 + 32; h++) {
        float4 wv = *(const float4*)(W1n + (size_t)h * HID + n);
        float x = s[h];
        a0 = fmaf(x, wv.x, a0);
        a1 = fmaf(x, wv.y, a1);
        a2 = fmaf(x, wv.z, a2);
        a3 = fmaf(x, wv.w, a3);
    }
    red[hq][c] = make_float4(a0, a1, a2, a3);
    __syncthreads();
    if (hq == 0) {
        float4 r0 = red[0][c], r1 = red[1][c], r2 = red[2][c], r3 = red[3][c];
        float4 o;
        o.x = r0.x + r1.x + r2.x + r3.x;
        o.y = r0.y + r1.y + r2.y + r3.y;
        o.z = r0.z + r1.z + r2.z + r3.z;
        o.w = r0.w + r1.w + r2.w + r3.w;
        *(float4*)(g_A + (size_t)bi * HID + n) = o;
    }
}

// ---------------------------------------------------------------------------
// Kernel B: pf = max_d(pairwise_feature); g_C[b][jk][:] = pf @ W1p + b1
// ---------------------------------------------------------------------------
__global__ void k_pair(const float* __restrict__ pfin,
                       const float* __restrict__ W1p,
                       const float* __restrict__ b1) {
    __shared__ float sP[8][NH];
    int row0 = blockIdx.x * 8;
    int b = row0 / NJK, jk0 = row0 % NJK;
    int t = threadIdx.x;

    for (int e = t; e < 8 * NH; e += 256) {
        int r = e >> 7, h = e & 127;
        const float* base = pfin + (((size_t)b * ND) * NJK + jk0 + r) * NH + h;
        float m = base[0];
#pragma unroll
        for (int d = 1; d < ND; d++)
            m = fmaxf(m, base[(size_t)d * NJK * NH]);
        sP[r][h] = m;
    }
    __syncthreads();

    int n = t * 2;
    float2 bv = *(const float2*)(b1 + n);
    float acc[8][2];
#pragma unroll
    for (int r = 0; r < 8; r++) { acc[r][0] = bv.x; acc[r][1] = bv.y; }

#pragma unroll 4
    for (int k = 0; k < NH; k++) {
        float2 w = *(const float2*)(W1p + (size_t)k * HID + n);
#pragma unroll
        for (int r = 0; r < 8; r++) {
            float x = sP[r][k];
            acc[r][0] = fmaf(x, w.x, acc[r][0]);
            acc[r][1] = fmaf(x, w.y, acc[r][1]);
        }
    }
#pragma unroll
    for (int r = 0; r < 8; r++)
        *(float2*)(g_C + ((size_t)b * NJK + jk0 + r) * HID + n) =
            make_float2(acc[r][0], acc[r][1]);
}

// ---------------------------------------------------------------------------
// Kernel T: g_W2h[n][k] = half(W2[k][n])
// ---------------------------------------------------------------------------
__global__ void k_w2h(const float* __restrict__ W2) {
    __shared__ float t[32][33];
    int n0 = blockIdx.x * 32, k0 = blockIdx.y * 32;
    int tx = threadIdx.x, ty = threadIdx.y;
#pragma unroll
    for (int r = ty; r < 32; r += 8)
        t[r][tx] = W2[(size_t)(k0 + r) * HID + n0 + tx];
    __syncthreads();
#pragma unroll
    for (int r = ty; r < 32; r += 8)
        g_W2h[(size_t)(n0 + r) * HID + k0 + tx] = __float2half(t[tx][r]);
}

// ---------------------------------------------------------------------------
// Kernel C: fp16 mma.sync, 512 threads, cooperative A-transform + ldmatrix.
//   16 warps: wm = wid&3 (M 32-blocks), wn = wid>>2 (N 64-blocks of 256-slice)
// ---------------------------------------------------------------------------
__global__ __launch_bounds__(THREADS, 1)
void k_main(const float* __restrict__ b2, const float* __restrict__ W3,
            const float* __restrict__ b3, const float* __restrict__ psc,
            const float* __restrict__ pbi, float* __restrict__ out) {
    extern __shared__ char smem[];
    int*    coff = (int*)(smem + SM_COFF);
    float*  sA   = (float*)(smem + SM_SA);
    float2* bw   = (float2*)(smem + SM_BW);
    float*  vred = (float*)(smem + SM_VRED);

    const uint32_t sbase = smem_u32(smem);
    const int tid = threadIdx.x;
    const int lane = tid & 31;
    const int wid = tid >> 5;
    const int g = lane >> 2, tig = lane & 3;
    const int wm = wid & 3, wn = wid >> 2;
    const int b = blockIdx.z;
    const int i = blockIdx.y;
    const int jk0 = blockIdx.x * TILE_M;

    if (tid < TILE_M) {
        int jk = jk0 + tid;
        if (jk > NJK - 1) jk = NJK - 1;
        coff[tid] = (b * NJK + jk) * HID;
    }
    {
        const float* ga = g_A + ((size_t)b * NNODE + i) * HID;
        for (int t = tid; t < HID; t += THREADS) sA[t] = ga[t];
        for (int n = tid; n < HID; n += THREADS) bw[n] = make_float2(b2[n], W3[n]);
    }
    __syncthreads();

    // ---- staging descriptors (2 C units + 2 B units per thread) ----
    int cm[2], bn[2], bf[2];
    const float* csrc[2];
    uint32_t adst[2], bdst[2];
#pragma unroll
    for (int q = 0; q < 2; q++) {
        int u = tid + q * THREADS;          // C: 1024 16B units
        cm[q] = u >> 3;
        int e = u & 7;
        csrc[q] = g_C + coff[cm[q]] + e * 4;
        adst[q] = (uint32_t)(cm[q] * (CST * 4) + e * 16);
        int v2 = tid + q * THREADS;         // B: 1024 16B units
        bn[q] = v2 >> 2;
        bf[q] = v2 & 3;
        bdst[q] = (uint32_t)(SM_BOFF + bn[q] * (BSTW * 4) + bf[q] * 16);
    }
    uint32_t stg[NSTG];
#pragma unroll
    for (int s = 0; s < NSTG; s++) stg[s] = sbase + SM_ST0 + s * STG_SZ;

    // ---- transform indices: row m, k-octet g8 ----
    const int tm = tid & 127;
    const int g8 = tid >> 7;

    // ---- ldmatrix lane address (constant part) ----
    const uint32_t arow = sbase + SM_AH +
        (uint32_t)((wm * 32 + (lane & 15)) * AHB + ((lane >> 4) << 4));

    float v[4] = {0.f, 0.f, 0.f, 0.f};

    for (int np = 0; np < NPASS; np++) {
        const int n0 = np * TILE_N;
        const __half* bsrc[2];
#pragma unroll
        for (int q = 0; q < 2; q++)
            bsrc[q] = g_W2h + (size_t)(n0 + bn[q]) * HID + bf[q] * 8;

        float acc[2][8][4];
#pragma unroll
        for (int mt = 0; mt < 2; mt++)
#pragma unroll
            for (int nt = 0; nt < 8; nt++)
#pragma unroll
                for (int j = 0; j < 4; j++) acc[mt][nt][j] = 0.f;

        // prologue: chunks 0, 1
#pragma unroll
        for (int c = 0; c < 2; c++) {
            const int kc = c * KCH;
            const uint32_t st = stg[c];
#pragma unroll
            for (int q = 0; q < 2; q++) cp16(st + adst[q], csrc[q] + kc);
#pragma unroll
            for (int q = 0; q < 2; q++) cp16(st + bdst[q], bsrc[q] + kc);
            cp_commit();
        }

        for (int c = 0; c < NCHUNKS; c++) {
            if (c < NCHUNKS - 1) cp_waitg<1>(); else cp_waitg<0>();
            __syncthreads();

            if (c + 2 < NCHUNKS) {
                const int kc = (c + 2) * KCH;
                const uint32_t st = stg[(c + 2) % NSTG];
#pragma unroll
                for (int q = 0; q < 2; q++) cp16(st + adst[q], csrc[q] + kc);
#pragma unroll
                for (int q = 0; q < 2; q++) cp16(st + bdst[q], bsrc[q] + kc);
                cp_commit();
            }

            // ---- cooperative A transform: f32 C + sA -> relu -> half ----
            {
                const float* Cs = (const float*)(smem + SM_ST0 + (c % NSTG) * STG_SZ);
                const float* cr = Cs + tm * CST + g8 * 8;
                float4 c0 = *(const float4*)(cr);
                float4 c1 = *(const float4*)(cr + 4);
                const float* ar = sA + c * KCH + g8 * 8;
                float4 a0 = *(const float4*)(ar);
                float4 a1 = *(const float4*)(ar + 4);
                uint4 o;
                o.x = h2pack(fmaxf(c0.x + a0.x, 0.f), fmaxf(c0.y + a0.y, 0.f));
                o.y = h2pack(fmaxf(c0.z + a0.z, 0.f), fmaxf(c0.w + a0.w, 0.f));
                o.z = h2pack(fmaxf(c1.x + a1.x, 0.f), fmaxf(c1.y + a1.y, 0.f));
                o.w = h2pack(fmaxf(c1.z + a1.z, 0.f), fmaxf(c1.w + a1.w, 0.f));
                *(uint4*)(smem + SM_AH + tm * AHB + g8 * 16) = o;
            }
            __syncthreads();

            // ---- compute chunk c ----
            const uint32_t* Bs =
                (const uint32_t*)(smem + SM_ST0 + (c % NSTG) * STG_SZ + SM_BOFF);
#pragma unroll
            for (int kst = 0; kst < 2; kst++) {
                uint32_t afr[2][4];
                ldmx4(afr[0], arow + kst * 32);
                ldmx4(afr[1], arow + kst * 32 + 16 * AHB);
#pragma unroll
                for (int nt = 0; nt < 8; nt++) {
                    const uint32_t* Bw = Bs + (wn * 64 + nt * 8 + g) * BSTW + kst * 8;
                    uint32_t b0 = Bw[tig];
                    uint32_t b1 = Bw[tig + 4];
                    mma_f16(acc[0][nt], afr[0], b0, b1);
                    mma_f16(acc[1][nt], afr[1], b0, b1);
                }
            }
        }
        __syncthreads();   // stage + Ah reuse safety across passes

        // epilogue accumulate: v += relu(acc + b2) * W3
#pragma unroll
        for (int mt = 0; mt < 2; mt++)
#pragma unroll
            for (int nt = 0; nt < 8; nt++)
#pragma unroll
                for (int j = 0; j < 4; j++) {
                    const int nl = wn * 64 + nt * 8 + tig * 2 + (j & 1);
                    float2 p = bw[n0 + nl];
                    v[mt * 2 + (j >> 1)] += fmaxf(acc[mt][nt][j] + p.x, 0.f) * p.y;
                }
    }

    // reduce over quad lanes; combine 4 wn groups via smem
#pragma unroll
    for (int r = 0; r < 4; r++) {
        v[r] += __shfl_xor_sync(0xffffffffu, v[r], 1);
        v[r] += __shfl_xor_sync(0xffffffffu, v[r], 2);
    }
    if (tig == 0) {
#pragma unroll
        for (int mt = 0; mt < 2; mt++)
#pragma unroll
            for (int half = 0; half < 2; half++)
                vred[wn * 128 + wm * 32 + mt * 16 + half * 8 + g] =
                    v[mt * 2 + half];
    }
    __syncthreads();

    if (tid < TILE_M && jk0 + tid < NJK) {
        float sum = vred[tid] + vred[128 + tid] + vred[256 + tid] + vred[384 + tid];
        float sc = __ldg(psc), bi2 = __ldg(pbi), b3v = __ldg(b3);
        float z = sc * (sum + b3v) + bi2;
        out[((size_t)b * NNODE + i) * NJK + jk0 + tid] = 1.f / (1.f + expf(-z));
    }
}

// ---------------------------------------------------------------------------
extern "C" void kernel_launch(void* const* d_in, const int* in_sizes, int n_in,
                              void* d_out, int out_size) {
    const float* node = (const float*)d_in[0];
    const float* pair = (const float*)d_in[1];
    const float* W1n  = (const float*)d_in[2];
    const float* W1p  = (const float*)d_in[3];
    const float* b1   = (const float*)d_in[4];
    const float* W2   = (const float*)d_in[5];
    const float* b2   = (const float*)d_in[6];
    const float* W3   = (const float*)d_in[7];
    const float* b3   = (const float*)d_in[8];
    const float* sc   = (const float*)d_in[9];
    const float* bi   = (const float*)d_in[10];
    float* out = (float*)d_out;

    cudaFuncSetAttribute(k_main, cudaFuncAttributeMaxDynamicSharedMemorySize,
                         SM_TOTAL);

    k_node<<<dim3(NB * NNODE, 4), NH>>>(node, W1n);
    k_pair<<<NB * NJK / 8, 256>>>(pair, W1p, b1);
    k_w2h<<<dim3(16, 16), dim3(32, 8)>>>(W2);

    dim3 grid(NJT, NNODE, NB);   // 13 x 40 x 2 = 1040 CTAs
    k_main<<<grid, 512, SM_TOTAL>>>(b2, W3, b3, sc, bi, out);
}

// round 10
// speedup vs baseline: 5.4571x; 1.0771x over previous
#include <cuda_runtime.h>
#include <cuda_fp16.h>
#include <cstdint>

#define NB 2
#define ND 8
#define NNODE 40
#define NH 128
#define HID 512
#define NJK (NNODE * NNODE)        // 1600
#define NJT 13                     // ceil(1600/128)
#define TILE_M 128
#define TILE_N 256
#define NPASS (HID / TILE_N)       // 2
#define KCH 32
#define NCHUNKS (HID / KCH)        // 16
#define NSTG 3
#define THREADS 512

#define CST 36                     // C stage row stride (f32 words)
#define BSTW 20                    // B stage row stride (b32 words = 40 halfs)
#define AHB 80                     // A-half row stride (bytes)
#define AHBUF 10240                // one A-half buffer (128*80)

// -------- device scratch --------
__device__ float  g_A[NB * NNODE * HID];   // hn        [b][i][k]
__device__ float  g_C[NB * NJK * HID];     // hp + b1   [b][jk][k]
__device__ __half g_W2h[HID * HID];        // W2^T      [n][k] half

// -------- dynamic smem layout (bytes) --------
#define SM_COFF   0                        // 128 ints
#define SM_SA     512                      // 512 f32
#define SM_BW     2560                     // 512 float2 (b2, W3)
#define SM_VRED   6656                     // 4*128 f32
#define SM_AH     8704                     // 2 x 10240 (double-buffered half tile)
#define SM_ST0    29696                    // stages, 1024-aligned
#define SM_BOFF   18432                    // B offset within stage (C = 128*144)
#define STG_SZ    38912                    // C 18432 + B 20480
#define SM_TOTAL  (SM_ST0 + NSTG * STG_SZ) // 146432

__device__ __forceinline__ uint32_t smem_u32(const void* p) {
    uint32_t a;
    asm("{ .reg .u64 t; cvta.to.shared.u64 t, %1; cvt.u32.u64 %0, t; }" : "=r"(a) : "l"(p));
    return a;
}
__device__ __forceinline__ uint32_t h2pack(float lo, float hi) {
    uint32_t r;
    asm("cvt.rn.f16x2.f32 %0, %1, %2;" : "=r"(r) : "f"(hi), "f"(lo));
    return r;
}
__device__ __forceinline__ void cp16(uint32_t dst, const void* src) {
    asm volatile("cp.async.cg.shared.global [%0], [%1], 16;" :: "r"(dst), "l"(src) : "memory");
}
__device__ __forceinline__ void cp_commit() {
    asm volatile("cp.async.commit_group;" ::: "memory");
}
template <int N>
__device__ __forceinline__ void cp_waitg() {
    asm volatile("cp.async.wait_group %0;" :: "n"(N) : "memory");
}
__device__ __forceinline__ void ldmx4(uint32_t* r, uint32_t addr) {
    asm volatile("ldmatrix.sync.aligned.m8n8.x4.shared.b16 {%0,%1,%2,%3}, [%4];"
                 : "=r"(r[0]), "=r"(r[1]), "=r"(r[2]), "=r"(r[3]) : "r"(addr));
}
__device__ __forceinline__ void mma_f16(float* d, const uint32_t* a,
                                        uint32_t b0, uint32_t b1) {
    asm volatile(
        "mma.sync.aligned.m16n8k16.row.col.f32.f16.f16.f32 "
        "{%0,%1,%2,%3}, {%4,%5,%6,%7}, {%8,%9}, {%0,%1,%2,%3};"
        : "+f"(d[0]), "+f"(d[1]), "+f"(d[2]), "+f"(d[3])
        : "r"(a[0]), "r"(a[1]), "r"(a[2]), "r"(a[3]), "r"(b0), "r"(b1));
}

// ---------------------------------------------------------------------------
// Kernel A: nf = max_d(node_feature); g_A[b][i][:] = nf @ W1n
// ---------------------------------------------------------------------------
__global__ void k_node(const float* __restrict__ nfin,
                       const float* __restrict__ W1n) {
    __shared__ float s[NH];
    __shared__ float4 red[4][32];
    int bi = blockIdx.x, nq = blockIdx.y;
    int b = bi / NNODE, i = bi % NNODE;
    int t = threadIdx.x;

    const float* base = nfin + (((size_t)b * ND) * NNODE + i) * NH + t;
    float m = base[0];
#pragma unroll
    for (int d = 1; d < ND; d++)
        m = fmaxf(m, base[(size_t)d * NNODE * NH]);
    s[t] = m;
    __syncthreads();

    int hq = t >> 5, c = t & 31;
    int n = nq * 128 + c * 4;
    float a0 = 0.f, a1 = 0.f, a2 = 0.f, a3 = 0.f;
#pragma unroll 8
    for (int h = hq * 32; h < hq * 32 + 32; h++) {
        float4 wv = *(const float4*)(W1n + (size_t)h * HID + n);
        float x = s[h];
        a0 = fmaf(x, wv.x, a0);
        a1 = fmaf(x, wv.y, a1);
        a2 = fmaf(x, wv.z, a2);
        a3 = fmaf(x, wv.w, a3);
    }
    red[hq][c] = make_float4(a0, a1, a2, a3);
    __syncthreads();
    if (hq == 0) {
        float4 r0 = red[0][c], r1 = red[1][c], r2 = red[2][c], r3 = red[3][c];
        float4 o;
        o.x = r0.x + r1.x + r2.x + r3.x;
        o.y = r0.y + r1.y + r2.y + r3.y;
        o.z = r0.z + r1.z + r2.z + r3.z;
        o.w = r0.w + r1.w + r2.w + r3.w;
        *(float4*)(g_A + (size_t)bi * HID + n) = o;
    }
}

// ---------------------------------------------------------------------------
// Kernel B: pf = max_d(pairwise_feature); g_C[b][jk][:] = pf @ W1p + b1
// ---------------------------------------------------------------------------
__global__ void k_pair(const float* __restrict__ pfin,
                       const float* __restrict__ W1p,
                       const float* __restrict__ b1) {
    __shared__ float sP[8][NH];
    int row0 = blockIdx.x * 8;
    int b = row0 / NJK, jk0 = row0 % NJK;
    int t = threadIdx.x;

    for (int e = t; e < 8 * NH; e += 256) {
        int r = e >> 7, h = e & 127;
        const float* base = pfin + (((size_t)b * ND) * NJK + jk0 + r) * NH + h;
        float m = base[0];
#pragma unroll
        for (int d = 1; d < ND; d++)
            m = fmaxf(m, base[(size_t)d * NJK * NH]);
        sP[r][h] = m;
    }
    __syncthreads();

    int n = t * 2;
    float2 bv = *(const float2*)(b1 + n);
    float acc[8][2];
#pragma unroll
    for (int r = 0; r < 8; r++) { acc[r][0] = bv.x; acc[r][1] = bv.y; }

#pragma unroll 4
    for (int k = 0; k < NH; k++) {
        float2 w = *(const float2*)(W1p + (size_t)k * HID + n);
#pragma unroll
        for (int r = 0; r < 8; r++) {
            float x = sP[r][k];
            acc[r][0] = fmaf(x, w.x, acc[r][0]);
            acc[r][1] = fmaf(x, w.y, acc[r][1]);
        }
    }
#pragma unroll
    for (int r = 0; r < 8; r++)
        *(float2*)(g_C + ((size_t)b * NJK + jk0 + r) * HID + n) =
            make_float2(acc[r][0], acc[r][1]);
}

// ---------------------------------------------------------------------------
// Kernel T: g_W2h[n][k] = half(W2[k][n])
// ---------------------------------------------------------------------------
__global__ void k_w2h(const float* __restrict__ W2) {
    __shared__ float t[32][33];
    int n0 = blockIdx.x * 32, k0 = blockIdx.y * 32;
    int tx = threadIdx.x, ty = threadIdx.y;
#pragma unroll
    for (int r = ty; r < 32; r += 8)
        t[r][tx] = W2[(size_t)(k0 + r) * HID + n0 + tx];
    __syncthreads();
#pragma unroll
    for (int r = ty; r < 32; r += 8)
        g_W2h[(size_t)(n0 + r) * HID + k0 + tx] = __float2half(t[tx][r]);
}

// ---------------------------------------------------------------------------
// Kernel C: fp16 mma.sync, overlap A-transform with MMA (double-buffered Ah),
// one barrier per chunk, ldmatrix for both operands.
// ---------------------------------------------------------------------------
__global__ __launch_bounds__(THREADS, 1)
void k_main(const float* __restrict__ b2, const float* __restrict__ W3,
            const float* __restrict__ b3, const float* __restrict__ psc,
            const float* __restrict__ pbi, float* __restrict__ out) {
    extern __shared__ char smem[];
    int*    coff = (int*)(smem + SM_COFF);
    float*  sA   = (float*)(smem + SM_SA);
    float2* bw   = (float2*)(smem + SM_BW);
    float*  vred = (float*)(smem + SM_VRED);

    const uint32_t sbase = smem_u32(smem);
    const int tid = threadIdx.x;
    const int lane = tid & 31;
    const int wid = tid >> 5;
    const int g = lane >> 2, tig = lane & 3;
    const int wm = wid & 3, wn = wid >> 2;
    const int b = blockIdx.z;
    const int i = blockIdx.y;
    const int jk0 = blockIdx.x * TILE_M;

    if (tid < TILE_M) {
        int jk = jk0 + tid;
        if (jk > NJK - 1) jk = NJK - 1;
        coff[tid] = (b * NJK + jk) * HID;
    }
    {
        const float* ga = g_A + ((size_t)b * NNODE + i) * HID;
        for (int t = tid; t < HID; t += THREADS) sA[t] = ga[t];
        for (int n = tid; n < HID; n += THREADS) bw[n] = make_float2(b2[n], W3[n]);
    }
    __syncthreads();

    // ---- staging descriptors (2 C units + 2 B units per thread) ----
    int cm[2], bn[2], bf[2];
    const float* csrc[2];
    uint32_t adst[2], bdst[2];
#pragma unroll
    for (int q = 0; q < 2; q++) {
        int u = tid + q * THREADS;
        cm[q] = u >> 3;
        int e = u & 7;
        csrc[q] = g_C + coff[cm[q]] + e * 4;
        adst[q] = (uint32_t)(cm[q] * (CST * 4) + e * 16);
        bn[q] = u >> 2;
        bf[q] = u & 3;
        bdst[q] = (uint32_t)(SM_BOFF + bn[q] * (BSTW * 4) + bf[q] * 16);
    }
    uint32_t stg[NSTG];
#pragma unroll
    for (int s = 0; s < NSTG; s++) stg[s] = sbase + SM_ST0 + s * STG_SZ;

    // ---- transform indices ----
    const int tm = tid & 127;
    const int g8 = tid >> 7;

    // ---- ldmatrix constant addresses ----
    const uint32_t arow = sbase + SM_AH +
        (uint32_t)((wm * 32 + (lane & 15)) * AHB + ((lane >> 4) << 4));
    const uint32_t bq = (uint32_t)(SM_BOFF +
        (wn * 64 + ((lane >> 4) << 3) + (lane & 7)) * (BSTW * 4) +
        (((lane >> 3) & 1) << 4));

    float v[4] = {0.f, 0.f, 0.f, 0.f};

    for (int np = 0; np < NPASS; np++) {
        const int n0 = np * TILE_N;
        const __half* bsrc[2];
#pragma unroll
        for (int q = 0; q < 2; q++)
            bsrc[q] = g_W2h + (size_t)(n0 + bn[q]) * HID + bf[q] * 8;

        float acc[2][8][4];
#pragma unroll
        for (int mt = 0; mt < 2; mt++)
#pragma unroll
            for (int nt = 0; nt < 8; nt++)
#pragma unroll
                for (int j = 0; j < 4; j++) acc[mt][nt][j] = 0.f;

        // prologue: issue chunks 0,1; transform chunk 0 into Ah[0]
#pragma unroll
        for (int c = 0; c < 2; c++) {
            const int kc = c * KCH;
            const uint32_t st = stg[c];
#pragma unroll
            for (int q = 0; q < 2; q++) cp16(st + adst[q], csrc[q] + kc);
#pragma unroll
            for (int q = 0; q < 2; q++) cp16(st + bdst[q], bsrc[q] + kc);
            cp_commit();
        }
        cp_waitg<0>();
        __syncthreads();
        {
            const float* Cs = (const float*)(smem + SM_ST0);
            const float* cr = Cs + tm * CST + g8 * 8;
            float4 c0 = *(const float4*)(cr);
            float4 c1 = *(const float4*)(cr + 4);
            const float* ar = sA + g8 * 8;
            float4 a0 = *(const float4*)(ar);
            float4 a1 = *(const float4*)(ar + 4);
            uint4 o;
            o.x = h2pack(fmaxf(c0.x + a0.x, 0.f), fmaxf(c0.y + a0.y, 0.f));
            o.y = h2pack(fmaxf(c0.z + a0.z, 0.f), fmaxf(c0.w + a0.w, 0.f));
            o.z = h2pack(fmaxf(c1.x + a1.x, 0.f), fmaxf(c1.y + a1.y, 0.f));
            o.w = h2pack(fmaxf(c1.z + a1.z, 0.f), fmaxf(c1.w + a1.w, 0.f));
            *(uint4*)(smem + SM_AH + tm * AHB + g8 * 16) = o;
        }

        for (int c = 0; c < NCHUNKS; c++) {
            __syncthreads();   // Ah[c&1] visible; prior stage/Ah reads done

            if (c + 2 < NCHUNKS) {
                const int kc = (c + 2) * KCH;
                const uint32_t st = stg[(c + 2) % NSTG];
#pragma unroll
                for (int q = 0; q < 2; q++) cp16(st + adst[q], csrc[q] + kc);
#pragma unroll
                for (int q = 0; q < 2; q++) cp16(st + bdst[q], bsrc[q] + kc);
                cp_commit();
                cp_waitg<1>();      // chunk c+1 data resident
            } else {
                cp_waitg<0>();
            }

            // ---- transform chunk c+1 into Ah[(c+1)&1] (overlaps MMA below) ----
            if (c + 1 < NCHUNKS) {
                const float* Cs =
                    (const float*)(smem + SM_ST0 + ((c + 1) % NSTG) * STG_SZ);
                const float* cr = Cs + tm * CST + g8 * 8;
                float4 c0 = *(const float4*)(cr);
                float4 c1 = *(const float4*)(cr + 4);
                const float* ar = sA + (c + 1) * KCH + g8 * 8;
                float4 a0 = *(const float4*)(ar);
                float4 a1 = *(const float4*)(ar + 4);
                uint4 o;
                o.x = h2pack(fmaxf(c0.x + a0.x, 0.f), fmaxf(c0.y + a0.y, 0.f));
                o.y = h2pack(fmaxf(c0.z + a0.z, 0.f), fmaxf(c0.w + a0.w, 0.f));
                o.z = h2pack(fmaxf(c1.x + a1.x, 0.f), fmaxf(c1.y + a1.y, 0.f));
                o.w = h2pack(fmaxf(c1.z + a1.z, 0.f), fmaxf(c1.w + a1.w, 0.f));
                *(uint4*)(smem + SM_AH + ((c + 1) & 1) * AHBUF + tm * AHB + g8 * 16) = o;
            }

            // ---- MMA chunk c ----
            const uint32_t stgb = sbase + SM_ST0 + (c % NSTG) * STG_SZ;
            const uint32_t aro = arow + (c & 1) * AHBUF;
#pragma unroll
            for (int kst = 0; kst < 2; kst++) {
                uint32_t afr[2][4];
                ldmx4(afr[0], aro + kst * 32);
                ldmx4(afr[1], aro + kst * 32 + 16 * AHB);
#pragma unroll
                for (int p = 0; p < 4; p++) {
                    uint32_t bfr[4];
                    ldmx4(bfr, stgb + bq + p * (16 * BSTW * 4) + kst * 32);
                    mma_f16(acc[0][2 * p], afr[0], bfr[0], bfr[1]);
                    mma_f16(acc[1][2 * p], afr[1], bfr[0], bfr[1]);
                    mma_f16(acc[0][2 * p + 1], afr[0], bfr[2], bfr[3]);
                    mma_f16(acc[1][2 * p + 1], afr[1], bfr[2], bfr[3]);
                }
            }
        }
        __syncthreads();   // stage + Ah reuse safety across passes

        // epilogue accumulate: v += relu(acc + b2) * W3
#pragma unroll
        for (int mt = 0; mt < 2; mt++)
#pragma unroll
            for (int nt = 0; nt < 8; nt++)
#pragma unroll
                for (int j = 0; j < 4; j++) {
                    const int nl = wn * 64 + nt * 8 + tig * 2 + (j & 1);
                    float2 p = bw[n0 + nl];
                    v[mt * 2 + (j >> 1)] += fmaxf(acc[mt][nt][j] + p.x, 0.f) * p.y;
                }
    }

    // reduce over quad lanes; combine 4 wn groups via smem
#pragma unroll
    for (int r = 0; r < 4; r++) {
        v[r] += __shfl_xor_sync(0xffffffffu, v[r], 1);
        v[r] += __shfl_xor_sync(0xffffffffu, v[r], 2);
    }
    if (tig == 0) {
#pragma unroll
        for (int mt = 0; mt < 2; mt++)
#pragma unroll
            for (int half = 0; half < 2; half++)
                vred[wn * 128 + wm * 32 + mt * 16 + half * 8 + g] =
                    v[mt * 2 + half];
    }
    __syncthreads();

    if (tid < TILE_M && jk0 + tid < NJK) {
        float sum = vred[tid] + vred[128 + tid] + vred[256 + tid] + vred[384 + tid];
        float sc = __ldg(psc), bi2 = __ldg(pbi), b3v = __ldg(b3);
        float z = sc * (sum + b3v) + bi2;
        out[((size_t)b * NNODE + i) * NJK + jk0 + tid] = 1.f / (1.f + expf(-z));
    }
}

// ---------------------------------------------------------------------------
extern "C" void kernel_launch(void* const* d_in, const int* in_sizes, int n_in,
                              void* d_out, int out_size) {
    const float* node = (const float*)d_in[0];
    const float* pair = (const float*)d_in[1];
    const float* W1n  = (const float*)d_in[2];
    const float* W1p  = (const float*)d_in[3];
    const float* b1   = (const float*)d_in[4];
    const float* W2   = (const float*)d_in[5];
    const float* b2   = (const float*)d_in[6];
    const float* W3   = (const float*)d_in[7];
    const float* b3   = (const float*)d_in[8];
    const float* sc   = (const float*)d_in[9];
    const float* bi   = (const float*)d_in[10];
    float* out = (float*)d_out;

    cudaFuncSetAttribute(k_main, cudaFuncAttributeMaxDynamicSharedMemorySize,
                         SM_TOTAL);

    k_node<<<dim3(NB * NNODE, 4), NH>>>(node, W1n);
    k_pair<<<NB * NJK / 8, 256>>>(pair, W1p, b1);
    k_w2h<<<dim3(16, 16), dim3(32, 8)>>>(W2);

    dim3 grid(NJT, NNODE, NB);   // 13 x 40 x 2 = 1040 CTAs
    k_main<<<grid, 512, SM_TOTAL>>>(b2, W3, b3, sc, bi, out);
}